// round 1
// baseline (speedup 1.0000x reference)
#include <cuda_runtime.h>
#include <cuda_bf16.h>
#include <cstdint>

// Problem constants
constexpr int N_TOK = 3072;
constexpr int D     = 1280;
constexpr int H     = 16;
constexpr int HK    = 80;     // head dim
constexpr int NSEG  = 8;
constexpr float SCALE = 0.111803398874989485f; // 80^-0.5

// ---------------- scratch (alloc-free rule: __device__ globals) ----------------
__device__ float g_qkv[N_TOK * 3 * D];          // [N][3][H][K]  (3*1280 = 3840 cols)
__device__ float g_q[H * N_TOK * HK];           // [H][N][K], rope applied
__device__ float g_k[H * N_TOK * HK];           // [H][N][K], rope applied
__device__ float g_v[H * N_TOK * HK];           // [H][N][K]
__device__ float g_attn[N_TOK * D];             // [N][H*K]

// ---------------- SIMT fp32 GEMM: C[M,NN] = A[M,KD] @ B[KD,NN] + bias ----------------
// BM=BN=128, BK=8, 256 threads, 8x8 microtile per thread.
template<int NN, int KD>
__global__ void __launch_bounds__(256) sgemm_bias_kernel(
    const float* __restrict__ A, const float* __restrict__ B,
    const float* __restrict__ bias, float* __restrict__ C)
{
    constexpr int BM = 128, BN = 128, BK = 8, TM = 8, TN = 8;
    __shared__ float As[BK][BM];
    __shared__ float Bs[BK][BN];

    const int tid = threadIdx.x;
    const int tr  = tid / 16;        // 0..15
    const int tc  = tid % 16;        // 0..15
    const int bm  = blockIdx.y * BM;
    const int bn  = blockIdx.x * BN;

    // A-tile load: 128 rows x 8 cols = 256 float4
    const int a_row = tid >> 1;
    const int a_col = (tid & 1) * 4;
    // B-tile load: 8 rows x 128 cols = 256 float4
    const int b_row = tid >> 5;
    const int b_col = (tid & 31) * 4;

    float acc[TM][TN];
    #pragma unroll
    for (int i = 0; i < TM; i++)
        #pragma unroll
        for (int j = 0; j < TN; j++) acc[i][j] = 0.f;

    for (int k0 = 0; k0 < KD; k0 += BK) {
        float4 av = *reinterpret_cast<const float4*>(&A[(size_t)(bm + a_row) * KD + k0 + a_col]);
        As[a_col + 0][a_row] = av.x;
        As[a_col + 1][a_row] = av.y;
        As[a_col + 2][a_row] = av.z;
        As[a_col + 3][a_row] = av.w;
        float4 bv = *reinterpret_cast<const float4*>(&B[(size_t)(k0 + b_row) * NN + bn + b_col]);
        *reinterpret_cast<float4*>(&Bs[b_row][b_col]) = bv;
        __syncthreads();

        #pragma unroll
        for (int kk = 0; kk < BK; kk++) {
            float ar[TM], br[TN];
            #pragma unroll
            for (int i = 0; i < TM; i++) ar[i] = As[kk][tr * TM + i];
            #pragma unroll
            for (int j = 0; j < TN; j++) br[j] = Bs[kk][tc * TN + j];
            #pragma unroll
            for (int i = 0; i < TM; i++)
                #pragma unroll
                for (int j = 0; j < TN; j++)
                    acc[i][j] += ar[i] * br[j];
        }
        __syncthreads();
    }

    // epilogue with bias, float4 stores
    #pragma unroll
    for (int i = 0; i < TM; i++) {
        const int row = bm + tr * TM + i;
        #pragma unroll
        for (int j4 = 0; j4 < TN; j4 += 4) {
            const int col = bn + tc * TN + j4;
            float4 o;
            o.x = acc[i][j4 + 0] + bias[col + 0];
            o.y = acc[i][j4 + 1] + bias[col + 1];
            o.z = acc[i][j4 + 2] + bias[col + 2];
            o.w = acc[i][j4 + 3] + bias[col + 3];
            *reinterpret_cast<float4*>(&C[(size_t)row * NN + col]) = o;
        }
    }
}

// ---------------- RoPE + split to head-major [H][N][K] ----------------
__global__ void __launch_bounds__(256) rope_split_kernel(
    const float* __restrict__ qkv, const float* __restrict__ cosNK,
    const float* __restrict__ sinNK,
    float* __restrict__ q, float* __restrict__ k, float* __restrict__ v)
{
    const int idx = blockIdx.x * blockDim.x + threadIdx.x;
    if (idx >= N_TOK * H * HK) return;
    const int kk = idx % HK;
    const int h  = (idx / HK) % H;
    const int n  = idx / (HK * H);

    const float c = cosNK[n * HK + kk];
    const float s = sinNK[n * HK + kk];

    const float* base = qkv + (size_t)n * 3 * H * HK;
    const int off  = h * HK + kk;
    const int kr   = (kk < HK / 2) ? kk + HK / 2 : kk - HK / 2;
    const float sg = (kk < HK / 2) ? -1.f : 1.f;
    const int offr = h * HK + kr;

    const float qv  = base[off];
    const float kv  = base[H * HK + off];
    const float vv  = base[2 * H * HK + off];
    const float qvr = base[offr];
    const float kvr = base[H * HK + offr];

    const size_t o = (size_t)h * N_TOK * HK + (size_t)n * HK + kk;
    q[o] = qv * c + sg * qvr * s;
    k[o] = kv * c + sg * kvr * s;
    v[o] = vv;
}

// ---------------- segment-masked flash attention ----------------
// grid: (N/32, H). block: 256 threads. 32-query tile, 32-key tiles, online softmax.
constexpr int QT = 32;
constexpr int KP = 81;   // smem stride pad (conflict-free across key rows)

__global__ void __launch_bounds__(256) attn_kernel(
    const float* __restrict__ q, const float* __restrict__ k,
    const float* __restrict__ v, const int* __restrict__ cu,
    float* __restrict__ attn)
{
    __shared__ float qs[QT][KP];
    __shared__ float ks[QT][KP];
    __shared__ float vs[QT][KP];
    __shared__ float sc[QT][QT + 1];
    __shared__ float mi[QT], li[QT], corr[QT];
    __shared__ int   rs[QT], re[QT];
    __shared__ int   blk_lo, blk_hi;

    const int h   = blockIdx.y;
    const int q0  = blockIdx.x * QT;
    const int tid = threadIdx.x;

    // per-row segment bounds
    if (tid < QT) {
        const int n = q0 + tid;
        int lo = 0, hi = N_TOK;
        #pragma unroll
        for (int sgi = 0; sgi < NSEG; sgi++) {
            const int a = cu[sgi], b = cu[sgi + 1];
            if (n >= a && n < b) { lo = a; hi = b; }
        }
        rs[tid] = lo; re[tid] = hi;
        mi[tid] = -1e30f; li[tid] = 0.f;
    }
    __syncthreads();
    if (tid == 0) {
        int lo = rs[0], hi = re[0];
        #pragma unroll
        for (int r = 1; r < QT; r++) { lo = min(lo, rs[r]); hi = max(hi, re[r]); }
        blk_lo = lo; blk_hi = hi;
    }
    // load q tile
    const float* qh = q + (size_t)h * N_TOK * HK;
    for (int i = tid; i < QT * HK; i += 256) {
        const int r = i / HK, c = i % HK;
        qs[r][c] = qh[(size_t)(q0 + r) * HK + c];
    }
    __syncthreads();

    const int arow = tid >> 3;          // 0..31
    const int ac0  = (tid & 7) * 10;    // 0,10,...,70
    float acc[10];
    #pragma unroll
    for (int c = 0; c < 10; c++) acc[c] = 0.f;

    const float* kh = k + (size_t)h * N_TOK * HK;
    const float* vh = v + (size_t)h * N_TOK * HK;
    const int lo = blk_lo, hi = blk_hi;

    for (int kc = lo; kc < hi; kc += QT) {
        // stage k/v tiles
        for (int i = tid; i < QT * HK; i += 256) {
            const int r = i / HK, c = i % HK;
            const int m = kc + r;
            const bool ok = (m < hi);
            ks[r][c] = ok ? kh[(size_t)m * HK + c] : 0.f;
            vs[r][c] = ok ? vh[(size_t)m * HK + c] : 0.f;
        }
        __syncthreads();

        // scores: thread handles (row = tid/8, 4 keys)
        {
            const int r  = tid >> 3;
            const int j0 = (tid & 7) * 4;
            float s0 = 0.f, s1 = 0.f, s2 = 0.f, s3 = 0.f;
            #pragma unroll
            for (int c = 0; c < HK; c++) {
                const float qv = qs[r][c];
                s0 += qv * ks[j0 + 0][c];
                s1 += qv * ks[j0 + 1][c];
                s2 += qv * ks[j0 + 2][c];
                s3 += qv * ks[j0 + 3][c];
            }
            const int a = rs[r], b = re[r];
            const int m0 = kc + j0;
            sc[r][j0 + 0] = (m0 + 0 >= a && m0 + 0 < b) ? s0 * SCALE : -1e30f;
            sc[r][j0 + 1] = (m0 + 1 >= a && m0 + 1 < b) ? s1 * SCALE : -1e30f;
            sc[r][j0 + 2] = (m0 + 2 >= a && m0 + 2 < b) ? s2 * SCALE : -1e30f;
            sc[r][j0 + 3] = (m0 + 3 >= a && m0 + 3 < b) ? s3 * SCALE : -1e30f;
        }
        __syncthreads();

        // online softmax update (one thread per row)
        if (tid < QT) {
            const int r = tid;
            float mx = -1e30f;
            #pragma unroll
            for (int j = 0; j < QT; j++) mx = fmaxf(mx, sc[r][j]);
            const float nm = fmaxf(mi[r], mx);
            const float cr = (nm == -1e30f) ? 1.f : __expf(mi[r] - nm);
            float sum = 0.f;
            #pragma unroll
            for (int j = 0; j < QT; j++) {
                const float sv = sc[r][j];
                const float p = (sv == -1e30f || nm == -1e30f) ? 0.f : __expf(sv - nm);
                sc[r][j] = p;
                sum += p;
            }
            li[r] = li[r] * cr + sum;
            mi[r] = nm;
            corr[r] = cr;
        }
        __syncthreads();

        // accumulate: thread owns (arow, 10 cols)
        {
            const float cr = corr[arow];
            #pragma unroll
            for (int c = 0; c < 10; c++) acc[c] *= cr;
            #pragma unroll
            for (int j = 0; j < QT; j++) {
                const float p = sc[arow][j];
                #pragma unroll
                for (int c = 0; c < 10; c++) acc[c] += p * vs[j][ac0 + c];
            }
        }
        __syncthreads();
    }

    // write attn output: [N][H*K]
    const float inv = 1.f / li[arow];
    float* dst = attn + (size_t)(q0 + arow) * (H * HK) + h * HK + ac0;
    #pragma unroll
    for (int c = 0; c < 10; c++) dst[c] = acc[c] * inv;
}

// ---------------- launch ----------------
extern "C" void kernel_launch(void* const* d_in, const int* in_sizes, int n_in,
                              void* d_out, int out_size)
{
    const float* hidden = (const float*)d_in[0];
    const int*   cu     = (const int*)  d_in[1];
    const float* cosNK  = (const float*)d_in[2];
    const float* sinNK  = (const float*)d_in[3];
    const float* qkv_w  = (const float*)d_in[4];
    const float* qkv_b  = (const float*)d_in[5];
    const float* proj_w = (const float*)d_in[6];
    const float* proj_b = (const float*)d_in[7];
    float* out = (float*)d_out;

    float *qkv, *q, *k, *v, *attn;
    cudaGetSymbolAddress((void**)&qkv,  g_qkv);
    cudaGetSymbolAddress((void**)&q,    g_q);
    cudaGetSymbolAddress((void**)&k,    g_k);
    cudaGetSymbolAddress((void**)&v,    g_v);
    cudaGetSymbolAddress((void**)&attn, g_attn);

    // 1) QKV GEMM + bias: [3072,1280] @ [1280,3840]
    sgemm_bias_kernel<3 * D, D><<<dim3((3 * D) / 128, N_TOK / 128), 256>>>(
        hidden, qkv_w, qkv_b, qkv);

    // 2) RoPE + head-major split
    {
        const int total = N_TOK * H * HK;
        rope_split_kernel<<<(total + 255) / 256, 256>>>(qkv, cosNK, sinNK, q, k, v);
    }

    // 3) segment-masked attention
    attn_kernel<<<dim3(N_TOK / QT, H), 256>>>(q, k, v, cu, attn);

    // 4) projection GEMM + bias: [3072,1280] @ [1280,1280] -> d_out
    sgemm_bias_kernel<D, D><<<dim3(D / 128, N_TOK / 128), 256>>>(
        attn, proj_w, proj_b, out);
}

// round 2
// speedup vs baseline: 1.1092x; 1.1092x over previous
#include <cuda_runtime.h>
#include <cuda_bf16.h>
#include <cstdint>

// Problem constants
constexpr int N_TOK = 3072;
constexpr int D     = 1280;
constexpr int H     = 16;
constexpr int HK    = 80;     // head dim
constexpr int NSEG  = 8;
constexpr float SCALE = 0.111803398874989485f; // 80^-0.5

// ---------------- scratch ----------------
__device__ float g_qkv[N_TOK * 3 * D];          // [N][3][H][K]
__device__ float g_q[H * N_TOK * HK];           // [H][N][K], rope applied
__device__ float g_k[H * N_TOK * HK];           // [H][N][K], rope applied
__device__ float g_v[H * N_TOK * HK];           // [H][N][K]
__device__ float g_attn[N_TOK * D];             // [N][H*K]

// ---------------- tf32 helpers ----------------
__device__ __forceinline__ uint32_t f2tf32(float x) {
    uint32_t r;
    asm("cvt.rna.tf32.f32 %0, %1;" : "=r"(r) : "f"(x));
    return r;
}

__device__ __forceinline__ void mma_tf32(float c[4], const uint32_t a[4], const uint32_t b[2]) {
    asm volatile(
        "mma.sync.aligned.m16n8k8.row.col.f32.tf32.tf32.f32 "
        "{%0,%1,%2,%3}, {%4,%5,%6,%7}, {%8,%9}, {%0,%1,%2,%3};"
        : "+f"(c[0]), "+f"(c[1]), "+f"(c[2]), "+f"(c[3])
        : "r"(a[0]), "r"(a[1]), "r"(a[2]), "r"(a[3]), "r"(b[0]), "r"(b[1]));
}

// ---------------- tf32 tensor-core GEMM: C[M,NN] = A[M,KD] @ B[KD,NN] + bias ----------------
// BM=BN=128, BK=32, 256 threads (8 warps, 2x4 grid of 64x32 warp tiles).
// Double-buffered smem (stride 136 => bank-conflict-free fragment loads), reg prefetch.
constexpr int GS = 32 * 136;   // one smem matrix buffer in uint32

template<int NN, int KD>
__global__ void __launch_bounds__(256) tgemm_bias_kernel(
    const float* __restrict__ A, const float* __restrict__ B,
    const float* __restrict__ bias, float* __restrict__ C)
{
    extern __shared__ uint32_t smem[];
    uint32_t* Asm = smem;            // [2][32][136] (k-major: [k][m])
    uint32_t* Bsm = smem + 2 * GS;   // [2][32][136] ([k][n])

    const int tid  = threadIdx.x;
    const int lane = tid & 31;
    const int w    = tid >> 5;
    const int wm   = w >> 2;   // 0..1
    const int wn   = w & 3;    // 0..3
    const int bm   = blockIdx.y * 128;
    const int bn   = blockIdx.x * 128;

    // A tile global-load mapping: row = tid>>1 (0..127), half = (tid&1)*16
    const int ar = tid >> 1;
    const int ac = (tid & 1) * 16;
    // B tile: krow = tid>>3 (0..31), colbase = (tid&7)*4, 4 col-block steps of 32
    const int br = tid >> 3;
    const int bc = (tid & 7) * 4;

    float4 apre[4], bpre[4];

    auto loadG = [&](int k0) {
        #pragma unroll
        for (int i = 0; i < 4; i++)
            apre[i] = *reinterpret_cast<const float4*>(&A[(size_t)(bm + ar) * KD + k0 + ac + 4 * i]);
        #pragma unroll
        for (int i = 0; i < 4; i++)
            bpre[i] = *reinterpret_cast<const float4*>(&B[(size_t)(k0 + br) * NN + bn + bc + 32 * i]);
    };
    auto storeS = [&](int buf) {
        uint32_t* as = Asm + buf * GS;
        uint32_t* bs = Bsm + buf * GS;
        #pragma unroll
        for (int i = 0; i < 4; i++) {
            const int c = ac + 4 * i;
            as[(c + 0) * 136 + ar] = f2tf32(apre[i].x);
            as[(c + 1) * 136 + ar] = f2tf32(apre[i].y);
            as[(c + 2) * 136 + ar] = f2tf32(apre[i].z);
            as[(c + 3) * 136 + ar] = f2tf32(apre[i].w);
        }
        #pragma unroll
        for (int i = 0; i < 4; i++) {
            uint4 t;
            t.x = f2tf32(bpre[i].x); t.y = f2tf32(bpre[i].y);
            t.z = f2tf32(bpre[i].z); t.w = f2tf32(bpre[i].w);
            *reinterpret_cast<uint4*>(&bs[br * 136 + bc + 32 * i]) = t;
        }
    };

    float acc[4][4][4] = {};

    loadG(0);
    storeS(0);
    __syncthreads();

    constexpr int KT = KD / 32;
    for (int kt = 0; kt < KT; kt++) {
        const int cur = kt & 1;
        if (kt + 1 < KT) loadG((kt + 1) * 32);

        const uint32_t* as = Asm + cur * GS;
        const uint32_t* bs = Bsm + cur * GS;

        #pragma unroll
        for (int kk = 0; kk < 32; kk += 8) {
            uint32_t af[4][4], bf[4][2];
            const int kA = (kk + (lane & 3)) * 136;
            const int kB = kA;
            #pragma unroll
            for (int mi = 0; mi < 4; mi++) {
                const int r0 = wm * 64 + mi * 16 + (lane >> 2);
                af[mi][0] = as[kA + r0];
                af[mi][1] = as[kA + r0 + 8];
                af[mi][2] = as[kA + 4 * 136 + r0];
                af[mi][3] = as[kA + 4 * 136 + r0 + 8];
            }
            #pragma unroll
            for (int ni = 0; ni < 4; ni++) {
                const int c0 = wn * 32 + ni * 8 + (lane >> 2);
                bf[ni][0] = bs[kB + c0];
                bf[ni][1] = bs[kB + 4 * 136 + c0];
            }
            #pragma unroll
            for (int mi = 0; mi < 4; mi++)
                #pragma unroll
                for (int ni = 0; ni < 4; ni++)
                    mma_tf32(acc[mi][ni], af[mi], bf[ni]);
        }
        __syncthreads();
        if (kt + 1 < KT) {
            storeS(cur ^ 1);
            __syncthreads();
        }
    }

    // epilogue: bias + store
    #pragma unroll
    for (int mi = 0; mi < 4; mi++) {
        const int row = bm + wm * 64 + mi * 16 + (lane >> 2);
        #pragma unroll
        for (int ni = 0; ni < 4; ni++) {
            const int col = bn + wn * 32 + ni * 8 + 2 * (lane & 3);
            const float2 bb = *reinterpret_cast<const float2*>(&bias[col]);
            float2 o0, o1;
            o0.x = acc[mi][ni][0] + bb.x; o0.y = acc[mi][ni][1] + bb.y;
            o1.x = acc[mi][ni][2] + bb.x; o1.y = acc[mi][ni][3] + bb.y;
            *reinterpret_cast<float2*>(&C[(size_t)row * NN + col]) = o0;
            *reinterpret_cast<float2*>(&C[(size_t)(row + 8) * NN + col]) = o1;
        }
    }
}

// ---------------- RoPE + split to head-major [H][N][K] ----------------
__global__ void __launch_bounds__(256) rope_split_kernel(
    const float* __restrict__ qkv, const float* __restrict__ cosNK,
    const float* __restrict__ sinNK,
    float* __restrict__ q, float* __restrict__ k, float* __restrict__ v)
{
    const int idx = blockIdx.x * blockDim.x + threadIdx.x;
    if (idx >= N_TOK * H * HK) return;
    const int kk = idx % HK;
    const int h  = (idx / HK) % H;
    const int n  = idx / (HK * H);

    const float c = cosNK[n * HK + kk];
    const float s = sinNK[n * HK + kk];

    const float* base = qkv + (size_t)n * 3 * H * HK;
    const int off  = h * HK + kk;
    const int kr   = (kk < HK / 2) ? kk + HK / 2 : kk - HK / 2;
    const float sg = (kk < HK / 2) ? -1.f : 1.f;
    const int offr = h * HK + kr;

    const float qv  = base[off];
    const float kv  = base[H * HK + off];
    const float vv  = base[2 * H * HK + off];
    const float qvr = base[offr];
    const float kvr = base[H * HK + offr];

    const size_t o = (size_t)h * N_TOK * HK + (size_t)n * HK + kk;
    q[o] = qv * c + sg * qvr * s;
    k[o] = kv * c + sg * kvr * s;
    v[o] = vv;
}

// ---------------- segment-masked flash attention (warp-per-row) ----------------
// grid: (N/32, H), block 256 (8 warps). Each warp owns rows {w, w+8, w+16, w+24}.
constexpr int QT = 32;
constexpr int KP = 81;   // odd stride => ks[lane][c] conflict-free (17*lane mod 32 permutes)

__global__ void __launch_bounds__(256) attn_kernel(
    const float* __restrict__ q, const float* __restrict__ k,
    const float* __restrict__ v, const int* __restrict__ cu,
    float* __restrict__ attn)
{
    __shared__ float qs[QT][KP];
    __shared__ float ks[QT][KP];
    __shared__ float vs[QT][KP];
    __shared__ int   rs[QT], re[QT];
    __shared__ int   blk_lo, blk_hi;

    const int h    = blockIdx.y;
    const int q0   = blockIdx.x * QT;
    const int tid  = threadIdx.x;
    const int w    = tid >> 5;
    const int lane = tid & 31;

    if (tid < QT) {
        const int n = q0 + tid;
        int lo = 0, hi = N_TOK;
        #pragma unroll
        for (int sgi = 0; sgi < NSEG; sgi++) {
            const int a = cu[sgi], b = cu[sgi + 1];
            if (n >= a && n < b) { lo = a; hi = b; }
        }
        rs[tid] = lo; re[tid] = hi;
    }
    __syncthreads();
    if (tid == 0) {
        int lo = rs[0], hi = re[0];
        #pragma unroll
        for (int r = 1; r < QT; r++) { lo = min(lo, rs[r]); hi = max(hi, re[r]); }
        blk_lo = lo; blk_hi = hi;
    }

    const float* qh = q + (size_t)h * N_TOK * HK;
    for (int i = tid; i < QT * HK; i += 256) {
        const int r = i / HK, c = i % HK;
        qs[r][c] = qh[(size_t)(q0 + r) * HK + c];
    }
    __syncthreads();

    float mi_[4], li_[4], acc[4][3];
    #pragma unroll
    for (int rr = 0; rr < 4; rr++) {
        mi_[rr] = -1e30f; li_[rr] = 0.f;
        acc[rr][0] = acc[rr][1] = acc[rr][2] = 0.f;
    }

    const float* kh = k + (size_t)h * N_TOK * HK;
    const float* vh = v + (size_t)h * N_TOK * HK;
    const int lo = blk_lo, hi = blk_hi;

    for (int kc = lo; kc < hi; kc += QT) {
        __syncthreads();  // protect ks/vs from previous iteration's readers
        for (int i = tid; i < QT * HK; i += 256) {
            const int r = i / HK, c = i % HK;
            const int m = kc + r;
            const bool ok = (m < hi);
            ks[r][c] = ok ? kh[(size_t)m * HK + c] : 0.f;
            vs[r][c] = ok ? vh[(size_t)m * HK + c] : 0.f;
        }
        __syncthreads();

        #pragma unroll
        for (int rr = 0; rr < 4; rr++) {
            const int r = w + rr * 8;
            float s = 0.f;
            #pragma unroll 8
            for (int c = 0; c < HK; c++) s += qs[r][c] * ks[lane][c];

            const int m = kc + lane;
            const bool ok = (m >= rs[r]) && (m < re[r]);
            s = ok ? s * SCALE : -1e30f;

            float mx = s;
            #pragma unroll
            for (int off = 16; off; off >>= 1) mx = fmaxf(mx, __shfl_xor_sync(0xffffffffu, mx, off));
            const float nm = fmaxf(mi_[rr], mx);

            float p = (s == -1e30f) ? 0.f : __expf(s - nm);
            float sum = p;
            #pragma unroll
            for (int off = 16; off; off >>= 1) sum += __shfl_xor_sync(0xffffffffu, sum, off);

            const float cr = (nm == -1e30f) ? 1.f : __expf(mi_[rr] - nm);
            li_[rr] = li_[rr] * cr + sum;
            mi_[rr] = nm;
            acc[rr][0] *= cr; acc[rr][1] *= cr; acc[rr][2] *= cr;

            #pragma unroll
            for (int j = 0; j < QT; j++) {
                const float pj = __shfl_sync(0xffffffffu, p, j);
                acc[rr][0] += pj * vs[j][lane];
                acc[rr][1] += pj * vs[j][lane + 32];
                acc[rr][2] += pj * vs[j][(lane & 15) + 64];  // only lanes<16 meaningful
            }
        }
    }

    #pragma unroll
    for (int rr = 0; rr < 4; rr++) {
        const int r = w + rr * 8;
        const float inv = 1.f / li_[rr];
        float* dst = attn + (size_t)(q0 + r) * (H * HK) + h * HK;
        dst[lane]      = acc[rr][0] * inv;
        dst[lane + 32] = acc[rr][1] * inv;
        if (lane < 16) dst[lane + 64] = acc[rr][2] * inv;
    }
}

// ---------------- launch ----------------
extern "C" void kernel_launch(void* const* d_in, const int* in_sizes, int n_in,
                              void* d_out, int out_size)
{
    const float* hidden = (const float*)d_in[0];
    const int*   cu     = (const int*)  d_in[1];
    const float* cosNK  = (const float*)d_in[2];
    const float* sinNK  = (const float*)d_in[3];
    const float* qkv_w  = (const float*)d_in[4];
    const float* qkv_b  = (const float*)d_in[5];
    const float* proj_w = (const float*)d_in[6];
    const float* proj_b = (const float*)d_in[7];
    float* out = (float*)d_out;

    float *qkv, *q, *k, *v, *attn;
    cudaGetSymbolAddress((void**)&qkv,  g_qkv);
    cudaGetSymbolAddress((void**)&q,    g_q);
    cudaGetSymbolAddress((void**)&k,    g_k);
    cudaGetSymbolAddress((void**)&v,    g_v);
    cudaGetSymbolAddress((void**)&attn, g_attn);

    const size_t smem_bytes = 4 * GS * sizeof(uint32_t);  // 69,632 B
    static bool attr_done = false;
    if (!attr_done) {
        cudaFuncSetAttribute(tgemm_bias_kernel<3 * D, D>,
                             cudaFuncAttributeMaxDynamicSharedMemorySize, (int)smem_bytes);
        cudaFuncSetAttribute(tgemm_bias_kernel<D, D>,
                             cudaFuncAttributeMaxDynamicSharedMemorySize, (int)smem_bytes);
        attr_done = true;
    }

    // 1) QKV GEMM + bias: [3072,1280] @ [1280,3840]
    tgemm_bias_kernel<3 * D, D><<<dim3((3 * D) / 128, N_TOK / 128), 256, smem_bytes>>>(
        hidden, qkv_w, qkv_b, qkv);

    // 2) RoPE + head-major split
    {
        const int total = N_TOK * H * HK;
        rope_split_kernel<<<(total + 255) / 256, 256>>>(qkv, cosNK, sinNK, q, k, v);
    }

    // 3) segment-masked attention
    attn_kernel<<<dim3(N_TOK / QT, H), 256>>>(q, k, v, cu, attn);

    // 4) projection GEMM + bias: [3072,1280] @ [1280,1280] -> d_out
    tgemm_bias_kernel<D, D><<<dim3(D / 128, N_TOK / 128), 256, smem_bytes>>>(
        attn, proj_w, proj_b, out);
}

// round 3
// speedup vs baseline: 2.0147x; 1.8165x over previous
#include <cuda_runtime.h>
#include <cuda_bf16.h>
#include <cstdint>

// Problem constants
constexpr int N_TOK = 3072;
constexpr int D     = 1280;
constexpr int H     = 16;
constexpr int HK    = 80;     // head dim
constexpr int NSEG  = 8;
constexpr float SCALE = 0.111803398874989485f; // 80^-0.5

// ---------------- scratch ----------------
__device__ float g_qkv[N_TOK * 3 * D];          // [N][3][H][K]
__device__ float g_q[H * N_TOK * HK];           // [H][N][K], rope applied
__device__ float g_k[H * N_TOK * HK];           // [H][N][K], rope applied
__device__ float g_v[H * N_TOK * HK];           // [H][N][K]
__device__ float g_attn[N_TOK * D];             // [N][H*K]

// ---------------- tf32 helpers ----------------
__device__ __forceinline__ uint32_t f2tf32(float x) {
    uint32_t r;
    asm("cvt.rna.tf32.f32 %0, %1;" : "=r"(r) : "f"(x));
    return r;
}

__device__ __forceinline__ void mma_tf32(float c[4], const uint32_t a[4], const uint32_t b[2]) {
    asm volatile(
        "mma.sync.aligned.m16n8k8.row.col.f32.tf32.tf32.f32 "
        "{%0,%1,%2,%3}, {%4,%5,%6,%7}, {%8,%9}, {%0,%1,%2,%3};"
        : "+f"(c[0]), "+f"(c[1]), "+f"(c[2]), "+f"(c[3])
        : "r"(a[0]), "r"(a[1]), "r"(a[2]), "r"(a[3]), "r"(b[0]), "r"(b[1]));
}

// ---------------- tf32 tensor-core GEMM (unchanged from round 2) ----------------
constexpr int GS = 32 * 136;   // one smem matrix buffer in uint32

template<int NN, int KD>
__global__ void __launch_bounds__(256) tgemm_bias_kernel(
    const float* __restrict__ A, const float* __restrict__ B,
    const float* __restrict__ bias, float* __restrict__ C)
{
    extern __shared__ uint32_t smem[];
    uint32_t* Asm = smem;            // [2][32][136] (k-major: [k][m])
    uint32_t* Bsm = smem + 2 * GS;   // [2][32][136] ([k][n])

    const int tid  = threadIdx.x;
    const int lane = tid & 31;
    const int w    = tid >> 5;
    const int wm   = w >> 2;   // 0..1
    const int wn   = w & 3;    // 0..3
    const int bm   = blockIdx.y * 128;
    const int bn   = blockIdx.x * 128;

    const int ar = tid >> 1;
    const int ac = (tid & 1) * 16;
    const int br = tid >> 3;
    const int bc = (tid & 7) * 4;

    float4 apre[4], bpre[4];

    auto loadG = [&](int k0) {
        #pragma unroll
        for (int i = 0; i < 4; i++)
            apre[i] = *reinterpret_cast<const float4*>(&A[(size_t)(bm + ar) * KD + k0 + ac + 4 * i]);
        #pragma unroll
        for (int i = 0; i < 4; i++)
            bpre[i] = *reinterpret_cast<const float4*>(&B[(size_t)(k0 + br) * NN + bn + bc + 32 * i]);
    };
    auto storeS = [&](int buf) {
        uint32_t* as = Asm + buf * GS;
        uint32_t* bs = Bsm + buf * GS;
        #pragma unroll
        for (int i = 0; i < 4; i++) {
            const int c = ac + 4 * i;
            as[(c + 0) * 136 + ar] = f2tf32(apre[i].x);
            as[(c + 1) * 136 + ar] = f2tf32(apre[i].y);
            as[(c + 2) * 136 + ar] = f2tf32(apre[i].z);
            as[(c + 3) * 136 + ar] = f2tf32(apre[i].w);
        }
        #pragma unroll
        for (int i = 0; i < 4; i++) {
            uint4 t;
            t.x = f2tf32(bpre[i].x); t.y = f2tf32(bpre[i].y);
            t.z = f2tf32(bpre[i].z); t.w = f2tf32(bpre[i].w);
            *reinterpret_cast<uint4*>(&bs[br * 136 + bc + 32 * i]) = t;
        }
    };

    float acc[4][4][4] = {};

    loadG(0);
    storeS(0);
    __syncthreads();

    constexpr int KT = KD / 32;
    for (int kt = 0; kt < KT; kt++) {
        const int cur = kt & 1;
        if (kt + 1 < KT) loadG((kt + 1) * 32);

        const uint32_t* as = Asm + cur * GS;
        const uint32_t* bs = Bsm + cur * GS;

        #pragma unroll
        for (int kk = 0; kk < 32; kk += 8) {
            uint32_t af[4][4], bf[4][2];
            const int kA = (kk + (lane & 3)) * 136;
            #pragma unroll
            for (int mi = 0; mi < 4; mi++) {
                const int r0 = wm * 64 + mi * 16 + (lane >> 2);
                af[mi][0] = as[kA + r0];
                af[mi][1] = as[kA + r0 + 8];
                af[mi][2] = as[kA + 4 * 136 + r0];
                af[mi][3] = as[kA + 4 * 136 + r0 + 8];
            }
            #pragma unroll
            for (int ni = 0; ni < 4; ni++) {
                const int c0 = wn * 32 + ni * 8 + (lane >> 2);
                bf[ni][0] = bs[kA + c0];
                bf[ni][1] = bs[kA + 4 * 136 + c0];
            }
            #pragma unroll
            for (int mi = 0; mi < 4; mi++)
                #pragma unroll
                for (int ni = 0; ni < 4; ni++)
                    mma_tf32(acc[mi][ni], af[mi], bf[ni]);
        }
        __syncthreads();
        if (kt + 1 < KT) {
            storeS(cur ^ 1);
            __syncthreads();
        }
    }

    #pragma unroll
    for (int mi = 0; mi < 4; mi++) {
        const int row = bm + wm * 64 + mi * 16 + (lane >> 2);
        #pragma unroll
        for (int ni = 0; ni < 4; ni++) {
            const int col = bn + wn * 32 + ni * 8 + 2 * (lane & 3);
            const float2 bb = *reinterpret_cast<const float2*>(&bias[col]);
            float2 o0, o1;
            o0.x = acc[mi][ni][0] + bb.x; o0.y = acc[mi][ni][1] + bb.y;
            o1.x = acc[mi][ni][2] + bb.x; o1.y = acc[mi][ni][3] + bb.y;
            *reinterpret_cast<float2*>(&C[(size_t)row * NN + col]) = o0;
            *reinterpret_cast<float2*>(&C[(size_t)(row + 8) * NN + col]) = o1;
        }
    }
}

// ---------------- RoPE + split to head-major [H][N][K] ----------------
__global__ void __launch_bounds__(256) rope_split_kernel(
    const float* __restrict__ qkv, const float* __restrict__ cosNK,
    const float* __restrict__ sinNK,
    float* __restrict__ q, float* __restrict__ k, float* __restrict__ v)
{
    const int idx = blockIdx.x * blockDim.x + threadIdx.x;
    if (idx >= N_TOK * H * HK) return;
    const int kk = idx % HK;
    const int h  = (idx / HK) % H;
    const int n  = idx / (HK * H);

    const float c = cosNK[n * HK + kk];
    const float s = sinNK[n * HK + kk];

    const float* base = qkv + (size_t)n * 3 * H * HK;
    const int off  = h * HK + kk;
    const int kr   = (kk < HK / 2) ? kk + HK / 2 : kk - HK / 2;
    const float sg = (kk < HK / 2) ? -1.f : 1.f;
    const int offr = h * HK + kr;

    const float qv  = base[off];
    const float kv  = base[H * HK + off];
    const float vv  = base[2 * H * HK + off];
    const float qvr = base[offr];
    const float kvr = base[H * HK + offr];

    const size_t o = (size_t)h * N_TOK * HK + (size_t)n * HK + kk;
    q[o] = qv * c + sg * qvr * s;
    k[o] = kv * c + sg * kvr * s;
    v[o] = vv;
}

// ---------------- mma-based segment-masked flash attention ----------------
// Block: 128 threads (4 warps), 32 queries x 1 head. 32-key tiles.
// QK^T: 3xtf32 (hi/lo) m16n8k8. Softmax: warp-per-8-rows shuffle. PV: tf32 mma.
constexpr int QT  = 32;
constexpr int KPQ = 84;  // q/k smem word stride: frag addr g*84+q -> g*20+q mod32: conflict-free
constexpr int KPV = 88;  // v smem word stride: frag addr q*88+g -> q*24+g mod32: conflict-free
constexpr int SCP = 36;  // score smem stride:  frag addr g*36+q -> g*4+q  mod32: conflict-free

constexpr int ATT_SMEM_WORDS =
    4 * QT * KPQ      // qhi, qlo, khi, klo
    + QT * KPV        // v (tf32)
    + QT * SCP        // scores / probs (float)
    + 3 * QT          // mi, li, corr
    + 2 * QT + 2;     // rs, re, blk bounds

__global__ void __launch_bounds__(128) attn_mma_kernel(
    const float* __restrict__ q, const float* __restrict__ k,
    const float* __restrict__ v, const int* __restrict__ cu,
    float* __restrict__ attn)
{
    extern __shared__ uint32_t sm[];
    uint32_t* qhi = sm;
    uint32_t* qlo = qhi + QT * KPQ;
    uint32_t* khi = qlo + QT * KPQ;
    uint32_t* klo = khi + QT * KPQ;
    uint32_t* vtf = klo + QT * KPQ;
    float*    sc  = (float*)(vtf + QT * KPV);
    float*    mi  = sc + QT * SCP;
    float*    li  = mi + QT;
    float*    corr= li + QT;
    int*      rs  = (int*)(corr + QT);
    int*      re  = rs + QT;
    int*      blk = re + QT;

    const int h    = blockIdx.y;
    const int q0   = blockIdx.x * QT;
    const int tid  = threadIdx.x;
    const int w    = tid >> 5;
    const int lane = tid & 31;
    const int g    = lane >> 2;     // 0..7
    const int qd   = lane & 3;      // 0..3
    const int wm   = w >> 1;        // m-tile (16 rows)
    const int wn   = w & 1;         // n-half

    // per-row segment bounds + stats init
    if (tid < QT) {
        const int n = q0 + tid;
        int lo = 0, hi = N_TOK;
        #pragma unroll
        for (int sgi = 0; sgi < NSEG; sgi++) {
            const int a = cu[sgi], b = cu[sgi + 1];
            if (n >= a && n < b) { lo = a; hi = b; }
        }
        rs[tid] = lo; re[tid] = hi;
        mi[tid] = -1e30f; li[tid] = 0.f;
    }
    __syncthreads();
    if (tid == 0) {
        int lo = rs[0], hi = re[0];
        #pragma unroll
        for (int r = 1; r < QT; r++) { lo = min(lo, rs[r]); hi = max(hi, re[r]); }
        blk[0] = lo; blk[1] = hi;
    }

    // stage Q (hi/lo tf32)
    const float* qh = q + (size_t)h * N_TOK * HK;
    for (int i = tid; i < QT * (HK / 4); i += 128) {
        const int r  = i / (HK / 4);
        const int c4 = (i % (HK / 4)) * 4;
        const float4 x = *reinterpret_cast<const float4*>(&qh[(size_t)(q0 + r) * HK + c4]);
        const float xs[4] = {x.x, x.y, x.z, x.w};
        #pragma unroll
        for (int e = 0; e < 4; e++) {
            const uint32_t hi_ = f2tf32(xs[e]);
            qhi[r * KPQ + c4 + e] = hi_;
            qlo[r * KPQ + c4 + e] = f2tf32(xs[e] - __uint_as_float(hi_));
        }
    }
    __syncthreads();

    const int lo = blk[0], hi = blk[1];
    const float* kh = k + (size_t)h * N_TOK * HK;
    const float* vh = v + (size_t)h * N_TOK * HK;

    float acc[5][4] = {};   // 16 rows x 40 cols per warp (5 n-tiles)

    for (int kc = lo; kc < hi; kc += QT) {
        // ---- stage K (hi/lo) and V (tf32), zero-fill past hi ----
        for (int i = tid; i < QT * (HK / 4); i += 128) {
            const int r  = i / (HK / 4);
            const int c4 = (i % (HK / 4)) * 4;
            const int m  = kc + r;
            float4 kx = {0.f, 0.f, 0.f, 0.f}, vx = {0.f, 0.f, 0.f, 0.f};
            if (m < hi) {
                kx = *reinterpret_cast<const float4*>(&kh[(size_t)m * HK + c4]);
                vx = *reinterpret_cast<const float4*>(&vh[(size_t)m * HK + c4]);
            }
            const float ks4[4] = {kx.x, kx.y, kx.z, kx.w};
            const float vs4[4] = {vx.x, vx.y, vx.z, vx.w};
            #pragma unroll
            for (int e = 0; e < 4; e++) {
                const uint32_t hi_ = f2tf32(ks4[e]);
                khi[r * KPQ + c4 + e] = hi_;
                klo[r * KPQ + c4 + e] = f2tf32(ks4[e] - __uint_as_float(hi_));
                vtf[r * KPV + c4 + e] = f2tf32(vs4[e]);
            }
        }
        __syncthreads();

        // ---- S = Q K^T (3xtf32), warp computes 16x16 quadrant ----
        {
            float s[2][4] = {};
            const int arow = wm * 16 + g;
            #pragma unroll
            for (int kk = 0; kk < HK; kk += 8) {
                uint32_t ahi[4], alo[4];
                ahi[0] = qhi[arow * KPQ + kk + qd];
                ahi[1] = qhi[(arow + 8) * KPQ + kk + qd];
                ahi[2] = qhi[arow * KPQ + kk + 4 + qd];
                ahi[3] = qhi[(arow + 8) * KPQ + kk + 4 + qd];
                alo[0] = qlo[arow * KPQ + kk + qd];
                alo[1] = qlo[(arow + 8) * KPQ + kk + qd];
                alo[2] = qlo[arow * KPQ + kk + 4 + qd];
                alo[3] = qlo[(arow + 8) * KPQ + kk + 4 + qd];
                #pragma unroll
                for (int nt = 0; nt < 2; nt++) {
                    const int bcol = wn * 16 + nt * 8 + g;
                    uint32_t bhi[2], blo2[2];
                    bhi[0]  = khi[bcol * KPQ + kk + qd];
                    bhi[1]  = khi[bcol * KPQ + kk + 4 + qd];
                    blo2[0] = klo[bcol * KPQ + kk + qd];
                    blo2[1] = klo[bcol * KPQ + kk + 4 + qd];
                    mma_tf32(s[nt], ahi, bhi);
                    mma_tf32(s[nt], ahi, blo2);
                    mma_tf32(s[nt], alo, bhi);
                }
            }
            #pragma unroll
            for (int nt = 0; nt < 2; nt++) {
                const int col = wn * 16 + nt * 8 + 2 * qd;
                *reinterpret_cast<float2*>(&sc[arow * SCP + col])       = make_float2(s[nt][0], s[nt][1]);
                *reinterpret_cast<float2*>(&sc[(arow + 8) * SCP + col]) = make_float2(s[nt][2], s[nt][3]);
            }
        }
        __syncthreads();

        // ---- softmax: warp w handles rows 8w..8w+7 ----
        #pragma unroll
        for (int rr = 0; rr < 8; rr++) {
            const int r = w * 8 + rr;
            const float sv = sc[r * SCP + lane];
            const int m = kc + lane;
            const bool ok = (m >= rs[r]) && (m < re[r]);
            float s = ok ? sv * SCALE : -1e30f;
            float mx = s;
            #pragma unroll
            for (int off = 16; off; off >>= 1) mx = fmaxf(mx, __shfl_xor_sync(0xffffffffu, mx, off));
            const float om = mi[r];
            const float nm = fmaxf(om, mx);
            const float p = ok ? __expf(s - nm) : 0.f;
            float sum = p;
            #pragma unroll
            for (int off = 16; off; off >>= 1) sum += __shfl_xor_sync(0xffffffffu, sum, off);
            const float cr = __expf(om - nm);
            sc[r * SCP + lane] = p;
            if (lane == 0) {
                mi[r] = nm;
                li[r] = li[r] * cr + sum;
                corr[r] = cr;
            }
        }
        __syncthreads();

        // ---- PV: acc = acc*corr + P V ----
        {
            const int arow = wm * 16 + g;
            const float c0 = corr[arow], c1 = corr[arow + 8];
            #pragma unroll
            for (int nt = 0; nt < 5; nt++) {
                acc[nt][0] *= c0; acc[nt][1] *= c0;
                acc[nt][2] *= c1; acc[nt][3] *= c1;
            }
            #pragma unroll
            for (int k8 = 0; k8 < QT; k8 += 8) {
                uint32_t a[4];
                a[0] = f2tf32(sc[arow * SCP + k8 + qd]);
                a[1] = f2tf32(sc[(arow + 8) * SCP + k8 + qd]);
                a[2] = f2tf32(sc[arow * SCP + k8 + 4 + qd]);
                a[3] = f2tf32(sc[(arow + 8) * SCP + k8 + 4 + qd]);
                #pragma unroll
                for (int nt = 0; nt < 5; nt++) {
                    const int n = wn * 40 + nt * 8 + g;
                    uint32_t b[2];
                    b[0] = vtf[(k8 + qd) * KPV + n];
                    b[1] = vtf[(k8 + qd + 4) * KPV + n];
                    mma_tf32(acc[nt], a, b);
                }
            }
        }
        __syncthreads();
    }

    // ---- epilogue: normalize, write [N][H*K] ----
    {
        const int arow = wm * 16 + g;
        const float inv0 = 1.f / li[arow];
        const float inv1 = 1.f / li[arow + 8];
        float* d0 = attn + (size_t)(q0 + arow) * (H * HK) + h * HK;
        float* d1 = attn + (size_t)(q0 + arow + 8) * (H * HK) + h * HK;
        #pragma unroll
        for (int nt = 0; nt < 5; nt++) {
            const int col = wn * 40 + nt * 8 + 2 * qd;
            *reinterpret_cast<float2*>(&d0[col]) = make_float2(acc[nt][0] * inv0, acc[nt][1] * inv0);
            *reinterpret_cast<float2*>(&d1[col]) = make_float2(acc[nt][2] * inv1, acc[nt][3] * inv1);
        }
    }
}

// ---------------- launch ----------------
extern "C" void kernel_launch(void* const* d_in, const int* in_sizes, int n_in,
                              void* d_out, int out_size)
{
    const float* hidden = (const float*)d_in[0];
    const int*   cu     = (const int*)  d_in[1];
    const float* cosNK  = (const float*)d_in[2];
    const float* sinNK  = (const float*)d_in[3];
    const float* qkv_w  = (const float*)d_in[4];
    const float* qkv_b  = (const float*)d_in[5];
    const float* proj_w = (const float*)d_in[6];
    const float* proj_b = (const float*)d_in[7];
    float* out = (float*)d_out;

    float *qkv, *q, *k, *v, *attn;
    cudaGetSymbolAddress((void**)&qkv,  g_qkv);
    cudaGetSymbolAddress((void**)&q,    g_q);
    cudaGetSymbolAddress((void**)&k,    g_k);
    cudaGetSymbolAddress((void**)&v,    g_v);
    cudaGetSymbolAddress((void**)&attn, g_attn);

    const size_t gemm_smem = 4 * GS * sizeof(uint32_t);       // 69,632 B
    const size_t attn_smem = ATT_SMEM_WORDS * sizeof(uint32_t);
    static bool attr_done = false;
    if (!attr_done) {
        cudaFuncSetAttribute(tgemm_bias_kernel<3 * D, D>,
                             cudaFuncAttributeMaxDynamicSharedMemorySize, (int)gemm_smem);
        cudaFuncSetAttribute(tgemm_bias_kernel<D, D>,
                             cudaFuncAttributeMaxDynamicSharedMemorySize, (int)gemm_smem);
        cudaFuncSetAttribute(attn_mma_kernel,
                             cudaFuncAttributeMaxDynamicSharedMemorySize, (int)attn_smem);
        attr_done = true;
    }

    // 1) QKV GEMM + bias
    tgemm_bias_kernel<3 * D, D><<<dim3((3 * D) / 128, N_TOK / 128), 256, gemm_smem>>>(
        hidden, qkv_w, qkv_b, qkv);

    // 2) RoPE + head-major split
    {
        const int total = N_TOK * H * HK;
        rope_split_kernel<<<(total + 255) / 256, 256>>>(qkv, cosNK, sinNK, q, k, v);
    }

    // 3) mma flash attention
    attn_mma_kernel<<<dim3(N_TOK / QT, H), 128, attn_smem>>>(q, k, v, cu, attn);

    // 4) projection GEMM + bias -> d_out
    tgemm_bias_kernel<D, D><<<dim3(D / 128, N_TOK / 128), 256, gemm_smem>>>(
        attn, proj_w, proj_b, out);
}

// round 4
// speedup vs baseline: 2.3594x; 1.1711x over previous
#include <cuda_runtime.h>
#include <cuda_bf16.h>
#include <cstdint>

// Problem constants
constexpr int N_TOK = 3072;
constexpr int D     = 1280;
constexpr int H     = 16;
constexpr int HK    = 80;     // head dim
constexpr int NSEG  = 8;
constexpr float SCALE = 0.111803398874989485f; // 80^-0.5

// ---------------- scratch ----------------
__device__ float    g_qkv[N_TOK * 3 * D];       // [N][3][H][K]
__device__ uint32_t g_qhi[H * N_TOK * HK];      // tf32 hi of rope(q), [H][N][K]
__device__ uint32_t g_qlo[H * N_TOK * HK];      // tf32 lo
__device__ uint32_t g_khi[H * N_TOK * HK];
__device__ uint32_t g_klo[H * N_TOK * HK];
__device__ uint32_t g_vtf[H * N_TOK * HK];      // tf32 of v
__device__ float    g_attn[N_TOK * D];          // [N][H*K]

// ---------------- tf32 helpers ----------------
__device__ __forceinline__ uint32_t f2tf32(float x) {
    uint32_t r;
    asm("cvt.rna.tf32.f32 %0, %1;" : "=r"(r) : "f"(x));
    return r;
}

__device__ __forceinline__ void mma_tf32(float c[4], const uint32_t a[4], const uint32_t b[2]) {
    asm volatile(
        "mma.sync.aligned.m16n8k8.row.col.f32.tf32.tf32.f32 "
        "{%0,%1,%2,%3}, {%4,%5,%6,%7}, {%8,%9}, {%0,%1,%2,%3};"
        : "+f"(c[0]), "+f"(c[1]), "+f"(c[2]), "+f"(c[3])
        : "r"(a[0]), "r"(a[1]), "r"(a[2]), "r"(a[3]), "r"(b[0]), "r"(b[1]));
}

// ---------------- tf32 tensor-core GEMM (unchanged) ----------------
constexpr int GS = 32 * 136;   // one smem matrix buffer in uint32

template<int NN, int KD>
__global__ void __launch_bounds__(256) tgemm_bias_kernel(
    const float* __restrict__ A, const float* __restrict__ B,
    const float* __restrict__ bias, float* __restrict__ C)
{
    extern __shared__ uint32_t smem[];
    uint32_t* Asm = smem;            // [2][32][136] (k-major: [k][m])
    uint32_t* Bsm = smem + 2 * GS;   // [2][32][136] ([k][n])

    const int tid  = threadIdx.x;
    const int lane = tid & 31;
    const int w    = tid >> 5;
    const int wm   = w >> 2;
    const int wn   = w & 3;
    const int bm   = blockIdx.y * 128;
    const int bn   = blockIdx.x * 128;

    const int ar = tid >> 1;
    const int ac = (tid & 1) * 16;
    const int br = tid >> 3;
    const int bc = (tid & 7) * 4;

    float4 apre[4], bpre[4];

    auto loadG = [&](int k0) {
        #pragma unroll
        for (int i = 0; i < 4; i++)
            apre[i] = *reinterpret_cast<const float4*>(&A[(size_t)(bm + ar) * KD + k0 + ac + 4 * i]);
        #pragma unroll
        for (int i = 0; i < 4; i++)
            bpre[i] = *reinterpret_cast<const float4*>(&B[(size_t)(k0 + br) * NN + bn + bc + 32 * i]);
    };
    auto storeS = [&](int buf) {
        uint32_t* as = Asm + buf * GS;
        uint32_t* bs = Bsm + buf * GS;
        #pragma unroll
        for (int i = 0; i < 4; i++) {
            const int c = ac + 4 * i;
            as[(c + 0) * 136 + ar] = f2tf32(apre[i].x);
            as[(c + 1) * 136 + ar] = f2tf32(apre[i].y);
            as[(c + 2) * 136 + ar] = f2tf32(apre[i].z);
            as[(c + 3) * 136 + ar] = f2tf32(apre[i].w);
        }
        #pragma unroll
        for (int i = 0; i < 4; i++) {
            uint4 t;
            t.x = f2tf32(bpre[i].x); t.y = f2tf32(bpre[i].y);
            t.z = f2tf32(bpre[i].z); t.w = f2tf32(bpre[i].w);
            *reinterpret_cast<uint4*>(&bs[br * 136 + bc + 32 * i]) = t;
        }
    };

    float acc[4][4][4] = {};

    loadG(0);
    storeS(0);
    __syncthreads();

    constexpr int KT = KD / 32;
    for (int kt = 0; kt < KT; kt++) {
        const int cur = kt & 1;
        if (kt + 1 < KT) loadG((kt + 1) * 32);

        const uint32_t* as = Asm + cur * GS;
        const uint32_t* bs = Bsm + cur * GS;

        #pragma unroll
        for (int kk = 0; kk < 32; kk += 8) {
            uint32_t af[4][4], bf[4][2];
            const int kA = (kk + (lane & 3)) * 136;
            #pragma unroll
            for (int mi = 0; mi < 4; mi++) {
                const int r0 = wm * 64 + mi * 16 + (lane >> 2);
                af[mi][0] = as[kA + r0];
                af[mi][1] = as[kA + r0 + 8];
                af[mi][2] = as[kA + 4 * 136 + r0];
                af[mi][3] = as[kA + 4 * 136 + r0 + 8];
            }
            #pragma unroll
            for (int ni = 0; ni < 4; ni++) {
                const int c0 = wn * 32 + ni * 8 + (lane >> 2);
                bf[ni][0] = bs[kA + c0];
                bf[ni][1] = bs[kA + 4 * 136 + c0];
            }
            #pragma unroll
            for (int mi = 0; mi < 4; mi++)
                #pragma unroll
                for (int ni = 0; ni < 4; ni++)
                    mma_tf32(acc[mi][ni], af[mi], bf[ni]);
        }
        __syncthreads();
        if (kt + 1 < KT) {
            storeS(cur ^ 1);
            __syncthreads();
        }
    }

    #pragma unroll
    for (int mi = 0; mi < 4; mi++) {
        const int row = bm + wm * 64 + mi * 16 + (lane >> 2);
        #pragma unroll
        for (int ni = 0; ni < 4; ni++) {
            const int col = bn + wn * 32 + ni * 8 + 2 * (lane & 3);
            const float2 bb = *reinterpret_cast<const float2*>(&bias[col]);
            float2 o0, o1;
            o0.x = acc[mi][ni][0] + bb.x; o0.y = acc[mi][ni][1] + bb.y;
            o1.x = acc[mi][ni][2] + bb.x; o1.y = acc[mi][ni][3] + bb.y;
            *reinterpret_cast<float2*>(&C[(size_t)row * NN + col]) = o0;
            *reinterpret_cast<float2*>(&C[(size_t)(row + 8) * NN + col]) = o1;
        }
    }
}

// ---------------- RoPE + split + tf32 hi/lo precompute ----------------
__global__ void __launch_bounds__(256) rope_split_kernel(
    const float* __restrict__ qkv, const float* __restrict__ cosNK,
    const float* __restrict__ sinNK,
    uint32_t* __restrict__ qhi, uint32_t* __restrict__ qlo,
    uint32_t* __restrict__ khi, uint32_t* __restrict__ klo,
    uint32_t* __restrict__ vtf)
{
    const int idx = blockIdx.x * blockDim.x + threadIdx.x;
    if (idx >= N_TOK * H * HK) return;
    const int kk = idx % HK;
    const int h  = (idx / HK) % H;
    const int n  = idx / (HK * H);

    const float c = cosNK[n * HK + kk];
    const float s = sinNK[n * HK + kk];

    const float* base = qkv + (size_t)n * 3 * H * HK;
    const int off  = h * HK + kk;
    const int kr   = (kk < HK / 2) ? kk + HK / 2 : kk - HK / 2;
    const float sg = (kk < HK / 2) ? -1.f : 1.f;
    const int offr = h * HK + kr;

    const float qv  = base[off];
    const float kv  = base[H * HK + off];
    const float vv  = base[2 * H * HK + off];
    const float qvr = base[offr];
    const float kvr = base[H * HK + offr];

    const float qr = qv * c + sg * qvr * s;
    const float kr2 = kv * c + sg * kvr * s;

    const size_t o = (size_t)h * N_TOK * HK + (size_t)n * HK + kk;
    const uint32_t qh_ = f2tf32(qr);
    const uint32_t kh_ = f2tf32(kr2);
    qhi[o] = qh_;
    qlo[o] = f2tf32(qr - __uint_as_float(qh_));
    khi[o] = kh_;
    klo[o] = f2tf32(kr2 - __uint_as_float(kh_));
    vtf[o] = f2tf32(vv);
}

// ---------------- mma flash attention: 64 queries/block, 8 warps ----------------
constexpr int QTQ = 64;   // queries per block
constexpr int KT  = 32;   // keys per tile
constexpr int KPQ = 84;   // q/k smem stride: (g*84+qd) mod 32 = 20g+qd -> conflict-free
constexpr int KPV = 88;   // v smem stride:   (qd*88+g) mod 32 = 24qd+g -> conflict-free
constexpr int SCP = 36;   // score stride:    (g*36+qd) mod 32 = 4g+qd  -> conflict-free

constexpr int ATT_SMEM_WORDS =
    2 * QTQ * KPQ     // qhi, qlo
    + 2 * KT * KPQ    // khi, klo
    + KT * KPV        // v
    + QTQ * SCP       // scores / probs
    + 3 * QTQ         // mi, li, corr
    + 2 * QTQ + 2;    // rs, re, blk

__global__ void __launch_bounds__(256) attn_mma_kernel(
    const uint32_t* __restrict__ gqhi, const uint32_t* __restrict__ gqlo,
    const uint32_t* __restrict__ gkhi, const uint32_t* __restrict__ gklo,
    const uint32_t* __restrict__ gvtf, const int* __restrict__ cu,
    float* __restrict__ attn)
{
    extern __shared__ uint32_t sm[];
    uint32_t* qhi = sm;
    uint32_t* qlo = qhi + QTQ * KPQ;
    uint32_t* khi = qlo + QTQ * KPQ;
    uint32_t* klo = khi + KT * KPQ;
    uint32_t* vtf = klo + KT * KPQ;
    float*    sc  = (float*)(vtf + KT * KPV);
    float*    mi  = sc + QTQ * SCP;
    float*    li  = mi + QTQ;
    float*    corr= li + QTQ;
    int*      rs  = (int*)(corr + QTQ);
    int*      re  = rs + QTQ;
    int*      blk = re + QTQ;

    const int h    = blockIdx.y;
    const int q0   = blockIdx.x * QTQ;
    const int tid  = threadIdx.x;
    const int w    = tid >> 5;
    const int lane = tid & 31;
    const int g    = lane >> 2;     // 0..7
    const int qd   = lane & 3;      // 0..3
    const int wm   = w >> 1;        // 0..3 -> 16-row slab
    const int wn   = w & 1;         // 0..1

    if (tid < QTQ) {
        const int n = q0 + tid;
        int lo = 0, hi = N_TOK;
        #pragma unroll
        for (int sgi = 0; sgi < NSEG; sgi++) {
            const int a = cu[sgi], b = cu[sgi + 1];
            if (n >= a && n < b) { lo = a; hi = b; }
        }
        rs[tid] = lo; re[tid] = hi;
        mi[tid] = -1e30f; li[tid] = 0.f;
    }
    __syncthreads();
    if (tid == 0) {
        int lo = rs[0], hi = re[0];
        #pragma unroll
        for (int r = 1; r < QTQ; r++) { lo = min(lo, rs[r]); hi = max(hi, re[r]); }
        blk[0] = lo; blk[1] = hi;
    }

    // stage Q (pure copies, uint4)
    const size_t hbase = (size_t)h * N_TOK * HK;
    for (int i = tid; i < QTQ * (HK / 4); i += 256) {
        const int r  = i / (HK / 4);
        const int c4 = (i % (HK / 4)) * 4;
        const size_t go = hbase + (size_t)(q0 + r) * HK + c4;
        *reinterpret_cast<uint4*>(&qhi[r * KPQ + c4]) = *reinterpret_cast<const uint4*>(&gqhi[go]);
        *reinterpret_cast<uint4*>(&qlo[r * KPQ + c4]) = *reinterpret_cast<const uint4*>(&gqlo[go]);
    }
    __syncthreads();

    const int lo = blk[0], hi = blk[1];
    float acc[5][4] = {};   // 16 rows x 40 cols per warp

    for (int kc = lo; kc < hi; kc += KT) {
        // ---- stage K hi/lo + V (pure copies) ----
        for (int i = tid; i < KT * (HK / 4); i += 256) {
            const int r  = i / (HK / 4);
            const int c4 = (i % (HK / 4)) * 4;
            const int m  = kc + r;
            uint4 kh4 = {0, 0, 0, 0}, kl4 = {0, 0, 0, 0}, vv4 = {0, 0, 0, 0};
            if (m < hi) {
                const size_t go = hbase + (size_t)m * HK + c4;
                kh4 = *reinterpret_cast<const uint4*>(&gkhi[go]);
                kl4 = *reinterpret_cast<const uint4*>(&gklo[go]);
                vv4 = *reinterpret_cast<const uint4*>(&gvtf[go]);
            }
            *reinterpret_cast<uint4*>(&khi[r * KPQ + c4]) = kh4;
            *reinterpret_cast<uint4*>(&klo[r * KPQ + c4]) = kl4;
            *reinterpret_cast<uint4*>(&vtf[r * KPV + c4]) = vv4;
        }
        __syncthreads();

        // ---- S = Q K^T (3xtf32); warp computes 16x16 quadrant of 64x32 ----
        {
            float s[2][4] = {};
            const int arow = wm * 16 + g;
            #pragma unroll
            for (int kk = 0; kk < HK; kk += 8) {
                uint32_t ahi[4], alo[4];
                ahi[0] = qhi[arow * KPQ + kk + qd];
                ahi[1] = qhi[(arow + 8) * KPQ + kk + qd];
                ahi[2] = qhi[arow * KPQ + kk + 4 + qd];
                ahi[3] = qhi[(arow + 8) * KPQ + kk + 4 + qd];
                alo[0] = qlo[arow * KPQ + kk + qd];
                alo[1] = qlo[(arow + 8) * KPQ + kk + qd];
                alo[2] = qlo[arow * KPQ + kk + 4 + qd];
                alo[3] = qlo[(arow + 8) * KPQ + kk + 4 + qd];
                #pragma unroll
                for (int nt = 0; nt < 2; nt++) {
                    const int bcol = wn * 16 + nt * 8 + g;
                    uint32_t bhi[2], blo2[2];
                    bhi[0]  = khi[bcol * KPQ + kk + qd];
                    bhi[1]  = khi[bcol * KPQ + kk + 4 + qd];
                    blo2[0] = klo[bcol * KPQ + kk + qd];
                    blo2[1] = klo[bcol * KPQ + kk + 4 + qd];
                    mma_tf32(s[nt], ahi, bhi);
                    mma_tf32(s[nt], ahi, blo2);
                    mma_tf32(s[nt], alo, bhi);
                }
            }
            #pragma unroll
            for (int nt = 0; nt < 2; nt++) {
                const int col = wn * 16 + nt * 8 + 2 * qd;
                *reinterpret_cast<float2*>(&sc[arow * SCP + col])       = make_float2(s[nt][0], s[nt][1]);
                *reinterpret_cast<float2*>(&sc[(arow + 8) * SCP + col]) = make_float2(s[nt][2], s[nt][3]);
            }
        }
        __syncthreads();

        // ---- softmax: warp w handles rows 8w..8w+7 ----
        #pragma unroll
        for (int rr = 0; rr < 8; rr++) {
            const int r = w * 8 + rr;
            const float sv = sc[r * SCP + lane];
            const int m = kc + lane;
            const bool ok = (m >= rs[r]) && (m < re[r]);
            float s = ok ? sv * SCALE : -1e30f;
            float mx = s;
            #pragma unroll
            for (int off = 16; off; off >>= 1) mx = fmaxf(mx, __shfl_xor_sync(0xffffffffu, mx, off));
            const float om = mi[r];
            const float nm = fmaxf(om, mx);
            const float p = ok ? __expf(s - nm) : 0.f;
            float sum = p;
            #pragma unroll
            for (int off = 16; off; off >>= 1) sum += __shfl_xor_sync(0xffffffffu, sum, off);
            const float cr = __expf(om - nm);
            sc[r * SCP + lane] = p;
            if (lane == 0) {
                mi[r] = nm;
                li[r] = li[r] * cr + sum;
                corr[r] = cr;
            }
        }
        __syncthreads();

        // ---- PV: acc = acc*corr + P V ----
        {
            const int arow = wm * 16 + g;
            const float c0 = corr[arow], c1 = corr[arow + 8];
            #pragma unroll
            for (int nt = 0; nt < 5; nt++) {
                acc[nt][0] *= c0; acc[nt][1] *= c0;
                acc[nt][2] *= c1; acc[nt][3] *= c1;
            }
            #pragma unroll
            for (int k8 = 0; k8 < KT; k8 += 8) {
                uint32_t a[4];
                a[0] = f2tf32(sc[arow * SCP + k8 + qd]);
                a[1] = f2tf32(sc[(arow + 8) * SCP + k8 + qd]);
                a[2] = f2tf32(sc[arow * SCP + k8 + 4 + qd]);
                a[3] = f2tf32(sc[(arow + 8) * SCP + k8 + 4 + qd]);
                #pragma unroll
                for (int nt = 0; nt < 5; nt++) {
                    const int n = wn * 40 + nt * 8 + g;
                    uint32_t b[2];
                    b[0] = vtf[(k8 + qd) * KPV + n];
                    b[1] = vtf[(k8 + qd + 4) * KPV + n];
                    mma_tf32(acc[nt], a, b);
                }
            }
        }
        __syncthreads();
    }

    // ---- epilogue ----
    {
        const int arow = wm * 16 + g;
        const float inv0 = 1.f / li[arow];
        const float inv1 = 1.f / li[arow + 8];
        float* d0 = attn + (size_t)(q0 + arow) * (H * HK) + h * HK;
        float* d1 = attn + (size_t)(q0 + arow + 8) * (H * HK) + h * HK;
        #pragma unroll
        for (int nt = 0; nt < 5; nt++) {
            const int col = wn * 40 + nt * 8 + 2 * qd;
            *reinterpret_cast<float2*>(&d0[col]) = make_float2(acc[nt][0] * inv0, acc[nt][1] * inv0);
            *reinterpret_cast<float2*>(&d1[col]) = make_float2(acc[nt][2] * inv1, acc[nt][3] * inv1);
        }
    }
}

// ---------------- launch ----------------
extern "C" void kernel_launch(void* const* d_in, const int* in_sizes, int n_in,
                              void* d_out, int out_size)
{
    const float* hidden = (const float*)d_in[0];
    const int*   cu     = (const int*)  d_in[1];
    const float* cosNK  = (const float*)d_in[2];
    const float* sinNK  = (const float*)d_in[3];
    const float* qkv_w  = (const float*)d_in[4];
    const float* qkv_b  = (const float*)d_in[5];
    const float* proj_w = (const float*)d_in[6];
    const float* proj_b = (const float*)d_in[7];
    float* out = (float*)d_out;

    float *qkv, *attn;
    uint32_t *qhi, *qlo, *khi, *klo, *vtf;
    cudaGetSymbolAddress((void**)&qkv,  g_qkv);
    cudaGetSymbolAddress((void**)&qhi,  g_qhi);
    cudaGetSymbolAddress((void**)&qlo,  g_qlo);
    cudaGetSymbolAddress((void**)&khi,  g_khi);
    cudaGetSymbolAddress((void**)&klo,  g_klo);
    cudaGetSymbolAddress((void**)&vtf,  g_vtf);
    cudaGetSymbolAddress((void**)&attn, g_attn);

    const size_t gemm_smem = 4 * GS * sizeof(uint32_t);
    const size_t attn_smem = ATT_SMEM_WORDS * sizeof(uint32_t);
    static bool attr_done = false;
    if (!attr_done) {
        cudaFuncSetAttribute(tgemm_bias_kernel<3 * D, D>,
                             cudaFuncAttributeMaxDynamicSharedMemorySize, (int)gemm_smem);
        cudaFuncSetAttribute(tgemm_bias_kernel<D, D>,
                             cudaFuncAttributeMaxDynamicSharedMemorySize, (int)gemm_smem);
        cudaFuncSetAttribute(attn_mma_kernel,
                             cudaFuncAttributeMaxDynamicSharedMemorySize, (int)attn_smem);
        attr_done = true;
    }

    // 1) QKV GEMM + bias
    tgemm_bias_kernel<3 * D, D><<<dim3((3 * D) / 128, N_TOK / 128), 256, gemm_smem>>>(
        hidden, qkv_w, qkv_b, qkv);

    // 2) RoPE + head-major split + tf32 precompute
    {
        const int total = N_TOK * H * HK;
        rope_split_kernel<<<(total + 255) / 256, 256>>>(
            qkv, cosNK, sinNK, qhi, qlo, khi, klo, vtf);
    }

    // 3) mma flash attention (64 queries/block)
    attn_mma_kernel<<<dim3(N_TOK / QTQ, H), 256, attn_smem>>>(
        qhi, qlo, khi, klo, vtf, cu, attn);

    // 4) projection GEMM + bias -> d_out
    tgemm_bias_kernel<D, D><<<dim3(D / 128, N_TOK / 128), 256, gemm_smem>>>(
        attn, proj_w, proj_b, out);
}

// round 5
// speedup vs baseline: 2.6171x; 1.1092x over previous
#include <cuda_runtime.h>
#include <cuda_bf16.h>
#include <cstdint>

// Problem constants
constexpr int N_TOK = 3072;
constexpr int D     = 1280;
constexpr int H     = 16;
constexpr int HK    = 80;     // head dim
constexpr int NSEG  = 8;
constexpr float SCALE = 0.111803398874989485f; // 80^-0.5

// ---------------- scratch ----------------
__device__ uint32_t g_hid_tf[N_TOK * D];        // tf32 of hidden
__device__ uint32_t g_qkvw_tf[D * 3 * D];       // tf32 of qkv_w
__device__ uint32_t g_projw_tf[D * D];          // tf32 of proj_w
__device__ float    g_qkv[N_TOK * 3 * D];       // [N][3][H][K] fp32
__device__ uint32_t g_qhi[H * N_TOK * HK];      // tf32 hi of SCALE*rope(q)
__device__ uint32_t g_qlo[H * N_TOK * HK];
__device__ uint32_t g_khi[H * N_TOK * HK];
__device__ uint32_t g_klo[H * N_TOK * HK];
__device__ uint32_t g_vtf[H * N_TOK * HK];
__device__ uint32_t g_attn_tf[N_TOK * D];       // tf32 of attention output [N][H*K]

// ---------------- helpers ----------------
__device__ __forceinline__ uint32_t f2tf32(float x) {
    uint32_t r;
    asm("cvt.rna.tf32.f32 %0, %1;" : "=r"(r) : "f"(x));
    return r;
}

__device__ __forceinline__ void mma_tf32(float c[4], const uint32_t a[4], const uint32_t b[2]) {
    asm volatile(
        "mma.sync.aligned.m16n8k8.row.col.f32.tf32.tf32.f32 "
        "{%0,%1,%2,%3}, {%4,%5,%6,%7}, {%8,%9}, {%0,%1,%2,%3};"
        : "+f"(c[0]), "+f"(c[1]), "+f"(c[2]), "+f"(c[3])
        : "r"(a[0]), "r"(a[1]), "r"(a[2]), "r"(a[3]), "r"(b[0]), "r"(b[1]));
}

__device__ __forceinline__ uint32_t smem_addr(const void* p) {
    return (uint32_t)__cvta_generic_to_shared(p);
}
#define CP_ASYNC16(dst, src) \
    asm volatile("cp.async.cg.shared.global [%0], [%1], 16;" :: "r"(dst), "l"(src))
#define CP_COMMIT() asm volatile("cp.async.commit_group;")
#define CP_WAIT1()  asm volatile("cp.async.wait_group 1;")

// ---------------- f32 -> tf32 bulk convert ----------------
__global__ void __launch_bounds__(256) f32_to_tf32_kernel(
    const float* __restrict__ s, uint32_t* __restrict__ d, int n4)
{
    const int i = blockIdx.x * blockDim.x + threadIdx.x;
    if (i >= n4) return;
    const float4 x = reinterpret_cast<const float4*>(s)[i];
    uint4 y;
    y.x = f2tf32(x.x); y.y = f2tf32(x.y); y.z = f2tf32(x.z); y.w = f2tf32(x.w);
    reinterpret_cast<uint4*>(d)[i] = y;
}

// ---------------- tf32 GEMM, cp.async 3-stage: C[M,NN]=A[M,KD]@B[KD,NN]+bias ----------------
// BM=BN=128, BK=32, 256 threads, 8 warps (2x4 of 64x32 warp tiles).
// A smem [m][k] stride 36 (frag addr 4g+qd conflict-free); B smem [k][n] stride 136 (8qd+g).
constexpr int ASTR = 36;
constexpr int BSTR = 136;
constexpr int A_WORDS = 128 * ASTR;          // 4608
constexpr int B_WORDS = 32 * BSTR;           // 4352
constexpr int STAGE_WORDS = A_WORDS + B_WORDS;
constexpr int GEMM_SMEM = 3 * STAGE_WORDS * 4;   // 107,520 B

template<int NN, int KD>
__global__ void __launch_bounds__(256) tgemm_tf32_kernel(
    const uint32_t* __restrict__ A, const uint32_t* __restrict__ B,
    const float* __restrict__ bias, float* __restrict__ C)
{
    extern __shared__ uint32_t smem[];

    const int tid  = threadIdx.x;
    const int lane = tid & 31;
    const int w    = tid >> 5;
    const int g    = lane >> 2;
    const int qd   = lane & 3;
    const int wm   = w >> 2;   // 0..1
    const int wn   = w & 3;    // 0..3
    const int bm   = blockIdx.y * 128;
    const int bn   = blockIdx.x * 128;

    // cp.async mappings
    const int ar = tid >> 1;            // 0..127
    const int ah = (tid & 1) * 16;      // 0 or 16 (k offset)
    const int br = tid >> 3;            // 0..31 (k row)
    const int bc = tid & 7;             // col chunk base

    auto issue = [&](int kt) {
        const int k0 = kt * 32;
        uint32_t* as = smem + (kt % 3) * STAGE_WORDS;
        uint32_t* bs = as + A_WORDS;
        #pragma unroll
        for (int i = 0; i < 4; i++) {
            const uint32_t dst = smem_addr(&as[ar * ASTR + ah + i * 4]);
            CP_ASYNC16(dst, &A[(size_t)(bm + ar) * KD + k0 + ah + i * 4]);
        }
        #pragma unroll
        for (int i = 0; i < 4; i++) {
            const int col = (bc + 8 * i) * 4;
            const uint32_t dst = smem_addr(&bs[br * BSTR + col]);
            CP_ASYNC16(dst, &B[(size_t)(k0 + br) * NN + bn + col]);
        }
        CP_COMMIT();
    };

    float acc[4][4][4] = {};

    issue(0);
    issue(1);

    constexpr int KT = KD / 32;
    for (int kt = 0; kt < KT; kt++) {
        CP_WAIT1();
        __syncthreads();
        if (kt + 2 < KT) issue(kt + 2);

        const uint32_t* as = smem + (kt % 3) * STAGE_WORDS;
        const uint32_t* bs = as + A_WORDS;

        #pragma unroll
        for (int kk = 0; kk < 32; kk += 8) {
            uint32_t af[4][4], bf[4][2];
            #pragma unroll
            for (int mi = 0; mi < 4; mi++) {
                const int r0 = (wm * 64 + mi * 16 + g) * ASTR;
                af[mi][0] = as[r0 + kk + qd];
                af[mi][1] = as[r0 + 8 * ASTR + kk + qd];
                af[mi][2] = as[r0 + kk + 4 + qd];
                af[mi][3] = as[r0 + 8 * ASTR + kk + 4 + qd];
            }
            #pragma unroll
            for (int ni = 0; ni < 4; ni++) {
                const int c0 = wn * 32 + ni * 8 + g;
                bf[ni][0] = bs[(kk + qd) * BSTR + c0];
                bf[ni][1] = bs[(kk + 4 + qd) * BSTR + c0];
            }
            #pragma unroll
            for (int mi = 0; mi < 4; mi++)
                #pragma unroll
                for (int ni = 0; ni < 4; ni++)
                    mma_tf32(acc[mi][ni], af[mi], bf[ni]);
        }
        __syncthreads();
    }

    #pragma unroll
    for (int mi = 0; mi < 4; mi++) {
        const int row = bm + wm * 64 + mi * 16 + g;
        #pragma unroll
        for (int ni = 0; ni < 4; ni++) {
            const int col = bn + wn * 32 + ni * 8 + 2 * qd;
            const float2 bb = *reinterpret_cast<const float2*>(&bias[col]);
            float2 o0, o1;
            o0.x = acc[mi][ni][0] + bb.x; o0.y = acc[mi][ni][1] + bb.y;
            o1.x = acc[mi][ni][2] + bb.x; o1.y = acc[mi][ni][3] + bb.y;
            *reinterpret_cast<float2*>(&C[(size_t)row * NN + col]) = o0;
            *reinterpret_cast<float2*>(&C[(size_t)(row + 8) * NN + col]) = o1;
        }
    }
}

// ---------------- RoPE + split + tf32 hi/lo precompute (q pre-scaled) ----------------
__global__ void __launch_bounds__(256) rope_split_kernel(
    const float* __restrict__ qkv, const float* __restrict__ cosNK,
    const float* __restrict__ sinNK,
    uint32_t* __restrict__ qhi, uint32_t* __restrict__ qlo,
    uint32_t* __restrict__ khi, uint32_t* __restrict__ klo,
    uint32_t* __restrict__ vtf)
{
    const int idx = blockIdx.x * blockDim.x + threadIdx.x;
    if (idx >= N_TOK * H * HK) return;
    const int kk = idx % HK;
    const int h  = (idx / HK) % H;
    const int n  = idx / (HK * H);

    const float c = cosNK[n * HK + kk];
    const float s = sinNK[n * HK + kk];

    const float* base = qkv + (size_t)n * 3 * H * HK;
    const int off  = h * HK + kk;
    const int kr   = (kk < HK / 2) ? kk + HK / 2 : kk - HK / 2;
    const float sg = (kk < HK / 2) ? -1.f : 1.f;
    const int offr = h * HK + kr;

    const float qv  = base[off];
    const float kv  = base[H * HK + off];
    const float vv  = base[2 * H * HK + off];
    const float qvr = base[offr];
    const float kvr = base[H * HK + offr];

    const float qr  = (qv * c + sg * qvr * s) * SCALE;   // fold in softmax scale
    const float kr2 = kv * c + sg * kvr * s;

    const size_t o = (size_t)h * N_TOK * HK + (size_t)n * HK + kk;
    const uint32_t qh_ = f2tf32(qr);
    const uint32_t kh_ = f2tf32(kr2);
    qhi[o] = qh_;
    qlo[o] = f2tf32(qr - __uint_as_float(qh_));
    khi[o] = kh_;
    klo[o] = f2tf32(kr2 - __uint_as_float(kh_));
    vtf[o] = f2tf32(vv);
}

// ---------------- mma flash attention: 64 q/block, 4 warps, register softmax ----------------
// Warp w owns rows w*16..w*16+15 (full 32 score cols, full 80 out cols).
constexpr int QTQ = 64;
constexpr int KTK = 32;
constexpr int KPQ = 84;   // q/k stride: 20g+qd conflict-free
constexpr int KPV = 88;   // v stride: 24qd+g conflict-free
constexpr int PST = 36;   // P stride: 4g+qd conflict-free

constexpr int ATT_SMEM_WORDS =
    2 * QTQ * KPQ       // qhi, qlo        10752
    + 2 * KTK * KPQ     // khi, klo         5376
    + KTK * KPV         // v                2816
    + 4 * 16 * PST      // P (per warp)     2304
    + 2 * QTQ + 2;      // rs, re, blk

__global__ void __launch_bounds__(128) attn_mma_kernel(
    const uint32_t* __restrict__ gqhi, const uint32_t* __restrict__ gqlo,
    const uint32_t* __restrict__ gkhi, const uint32_t* __restrict__ gklo,
    const uint32_t* __restrict__ gvtf, const int* __restrict__ cu,
    uint32_t* __restrict__ attn_tf)
{
    extern __shared__ uint32_t sm[];
    uint32_t* qhi = sm;
    uint32_t* qlo = qhi + QTQ * KPQ;
    uint32_t* khi = qlo + QTQ * KPQ;
    uint32_t* klo = khi + KTK * KPQ;
    uint32_t* vtf = klo + KTK * KPQ;
    uint32_t* psm = vtf + KTK * KPV;
    int*      rs  = (int*)(psm + 4 * 16 * PST);
    int*      re  = rs + QTQ;
    int*      blk = re + QTQ;

    const int h    = blockIdx.y;
    const int q0   = blockIdx.x * QTQ;
    const int tid  = threadIdx.x;
    const int w    = tid >> 5;
    const int lane = tid & 31;
    const int g    = lane >> 2;
    const int qd   = lane & 3;

    if (tid < QTQ) {
        const int n = q0 + tid;
        int lo = 0, hi = N_TOK;
        #pragma unroll
        for (int sgi = 0; sgi < NSEG; sgi++) {
            const int a = cu[sgi], b = cu[sgi + 1];
            if (n >= a && n < b) { lo = a; hi = b; }
        }
        rs[tid] = lo; re[tid] = hi;
    }
    __syncthreads();
    if (tid == 0) {
        int lo = rs[0], hi = re[0];
        #pragma unroll
        for (int r = 1; r < QTQ; r++) { lo = min(lo, rs[r]); hi = max(hi, re[r]); }
        blk[0] = lo; blk[1] = hi;
    }

    // stage Q (pure uint4 copies)
    const size_t hbase = (size_t)h * N_TOK * HK;
    for (int i = tid; i < QTQ * (HK / 4); i += 128) {
        const int r  = i / (HK / 4);
        const int c4 = (i % (HK / 4)) * 4;
        const size_t go = hbase + (size_t)(q0 + r) * HK + c4;
        *reinterpret_cast<uint4*>(&qhi[r * KPQ + c4]) = *reinterpret_cast<const uint4*>(&gqhi[go]);
        *reinterpret_cast<uint4*>(&qlo[r * KPQ + c4]) = *reinterpret_cast<const uint4*>(&gqlo[go]);
    }
    __syncthreads();

    const int rowA = w * 16 + g, rowB = rowA + 8;
    const int rsA = rs[rowA], reA = re[rowA];
    const int rsB = rs[rowB], reB = re[rowB];
    const int lo = blk[0], hi = blk[1];

    float miA = -1e30f, liA = 0.f, miB = -1e30f, liB = 0.f;
    float acc[10][4] = {};
    uint32_t* pw = psm + w * (16 * PST);

    for (int kc = lo; kc < hi; kc += KTK) {
        __syncthreads();   // previous tile's consumers done before overwrite
        for (int i = tid; i < KTK * (HK / 4); i += 128) {
            const int r  = i / (HK / 4);
            const int c4 = (i % (HK / 4)) * 4;
            const int m  = kc + r;
            uint4 kh4 = {0, 0, 0, 0}, kl4 = {0, 0, 0, 0}, vv4 = {0, 0, 0, 0};
            if (m < hi) {
                const size_t go = hbase + (size_t)m * HK + c4;
                kh4 = *reinterpret_cast<const uint4*>(&gkhi[go]);
                kl4 = *reinterpret_cast<const uint4*>(&gklo[go]);
                vv4 = *reinterpret_cast<const uint4*>(&gvtf[go]);
            }
            *reinterpret_cast<uint4*>(&khi[r * KPQ + c4]) = kh4;
            *reinterpret_cast<uint4*>(&klo[r * KPQ + c4]) = kl4;
            *reinterpret_cast<uint4*>(&vtf[r * KPV + c4]) = vv4;
        }
        __syncthreads();

        // ---- S = Q K^T (3xtf32): warp computes 16x32 strip ----
        float s[4][4] = {};
        #pragma unroll
        for (int kk = 0; kk < HK; kk += 8) {
            uint32_t ahi[4], alo[4];
            const int rA = rowA * KPQ, rB = rowB * KPQ;
            ahi[0] = qhi[rA + kk + qd];
            ahi[1] = qhi[rB + kk + qd];
            ahi[2] = qhi[rA + kk + 4 + qd];
            ahi[3] = qhi[rB + kk + 4 + qd];
            alo[0] = qlo[rA + kk + qd];
            alo[1] = qlo[rB + kk + qd];
            alo[2] = qlo[rA + kk + 4 + qd];
            alo[3] = qlo[rB + kk + 4 + qd];
            #pragma unroll
            for (int nt = 0; nt < 4; nt++) {
                const int bcol = (nt * 8 + g) * KPQ;
                uint32_t bhi[2], blo2[2];
                bhi[0]  = khi[bcol + kk + qd];
                bhi[1]  = khi[bcol + kk + 4 + qd];
                blo2[0] = klo[bcol + kk + qd];
                blo2[1] = klo[bcol + kk + 4 + qd];
                mma_tf32(s[nt], ahi, bhi);
                mma_tf32(s[nt], ahi, blo2);
                mma_tf32(s[nt], alo, bhi);
            }
        }

        // ---- register softmax (rows fully warp-local) ----
        float mxA = -1e30f, mxB = -1e30f;
        #pragma unroll
        for (int nt = 0; nt < 4; nt++) {
            const int c0 = kc + nt * 8 + 2 * qd;
            const int c1 = c0 + 1;
            mxA = fmaxf(mxA, fmaxf((c0 >= rsA && c0 < reA) ? s[nt][0] : -1e30f,
                                   (c1 >= rsA && c1 < reA) ? s[nt][1] : -1e30f));
            mxB = fmaxf(mxB, fmaxf((c0 >= rsB && c0 < reB) ? s[nt][2] : -1e30f,
                                   (c1 >= rsB && c1 < reB) ? s[nt][3] : -1e30f));
        }
        #pragma unroll
        for (int off = 1; off <= 2; off <<= 1) {
            mxA = fmaxf(mxA, __shfl_xor_sync(0xffffffffu, mxA, off));
            mxB = fmaxf(mxB, __shfl_xor_sync(0xffffffffu, mxB, off));
        }
        const float nmA = fmaxf(miA, mxA), nmB = fmaxf(miB, mxB);
        const float crA = __expf(miA - nmA), crB = __expf(miB - nmB);
        float sumA = 0.f, sumB = 0.f;
        #pragma unroll
        for (int nt = 0; nt < 4; nt++) {
            const int c0 = kc + nt * 8 + 2 * qd;
            const int c1 = c0 + 1;
            s[nt][0] = (c0 >= rsA && c0 < reA) ? __expf(s[nt][0] - nmA) : 0.f;
            s[nt][1] = (c1 >= rsA && c1 < reA) ? __expf(s[nt][1] - nmA) : 0.f;
            s[nt][2] = (c0 >= rsB && c0 < reB) ? __expf(s[nt][2] - nmB) : 0.f;
            s[nt][3] = (c1 >= rsB && c1 < reB) ? __expf(s[nt][3] - nmB) : 0.f;
            sumA += s[nt][0] + s[nt][1];
            sumB += s[nt][2] + s[nt][3];
        }
        #pragma unroll
        for (int off = 1; off <= 2; off <<= 1) {
            sumA += __shfl_xor_sync(0xffffffffu, sumA, off);
            sumB += __shfl_xor_sync(0xffffffffu, sumB, off);
        }
        liA = liA * crA + sumA; miA = nmA;
        liB = liB * crB + sumB; miB = nmB;

        #pragma unroll
        for (int nt = 0; nt < 10; nt++) {
            acc[nt][0] *= crA; acc[nt][1] *= crA;
            acc[nt][2] *= crB; acc[nt][3] *= crB;
        }

        // ---- P -> warp-private smem (tf32), then PV ----
        #pragma unroll
        for (int nt = 0; nt < 4; nt++) {
            const int cb = nt * 8 + 2 * qd;
            pw[g * PST + cb]           = f2tf32(s[nt][0]);
            pw[g * PST + cb + 1]       = f2tf32(s[nt][1]);
            pw[(g + 8) * PST + cb]     = f2tf32(s[nt][2]);
            pw[(g + 8) * PST + cb + 1] = f2tf32(s[nt][3]);
        }
        __syncwarp();

        #pragma unroll
        for (int k8 = 0; k8 < KTK; k8 += 8) {
            uint32_t a[4];
            a[0] = pw[g * PST + k8 + qd];
            a[1] = pw[(g + 8) * PST + k8 + qd];
            a[2] = pw[g * PST + k8 + 4 + qd];
            a[3] = pw[(g + 8) * PST + k8 + 4 + qd];
            #pragma unroll
            for (int nt = 0; nt < 10; nt++) {
                uint32_t b[2];
                b[0] = vtf[(k8 + qd) * KPV + nt * 8 + g];
                b[1] = vtf[(k8 + 4 + qd) * KPV + nt * 8 + g];
                mma_tf32(acc[nt], a, b);
            }
        }
        __syncwarp();   // protect pw before next tile's writes
    }

    // ---- epilogue: normalize, write tf32 [N][H*K] ----
    const float invA = 1.f / liA, invB = 1.f / liB;
    uint32_t* dA = attn_tf + (size_t)(q0 + rowA) * (H * HK) + h * HK;
    uint32_t* dB = attn_tf + (size_t)(q0 + rowB) * (H * HK) + h * HK;
    #pragma unroll
    for (int nt = 0; nt < 10; nt++) {
        const int col = nt * 8 + 2 * qd;
        dA[col]     = f2tf32(acc[nt][0] * invA);
        dA[col + 1] = f2tf32(acc[nt][1] * invA);
        dB[col]     = f2tf32(acc[nt][2] * invB);
        dB[col + 1] = f2tf32(acc[nt][3] * invB);
    }
}

// ---------------- launch ----------------
extern "C" void kernel_launch(void* const* d_in, const int* in_sizes, int n_in,
                              void* d_out, int out_size)
{
    const float* hidden = (const float*)d_in[0];
    const int*   cu     = (const int*)  d_in[1];
    const float* cosNK  = (const float*)d_in[2];
    const float* sinNK  = (const float*)d_in[3];
    const float* qkv_w  = (const float*)d_in[4];
    const float* qkv_b  = (const float*)d_in[5];
    const float* proj_w = (const float*)d_in[6];
    const float* proj_b = (const float*)d_in[7];
    float* out = (float*)d_out;

    float *qkv;
    uint32_t *hidtf, *qkvwtf, *projwtf, *qhi, *qlo, *khi, *klo, *vtf, *attntf;
    cudaGetSymbolAddress((void**)&hidtf,  g_hid_tf);
    cudaGetSymbolAddress((void**)&qkvwtf, g_qkvw_tf);
    cudaGetSymbolAddress((void**)&projwtf,g_projw_tf);
    cudaGetSymbolAddress((void**)&qkv,    g_qkv);
    cudaGetSymbolAddress((void**)&qhi,    g_qhi);
    cudaGetSymbolAddress((void**)&qlo,    g_qlo);
    cudaGetSymbolAddress((void**)&khi,    g_khi);
    cudaGetSymbolAddress((void**)&klo,    g_klo);
    cudaGetSymbolAddress((void**)&vtf,    g_vtf);
    cudaGetSymbolAddress((void**)&attntf, g_attn_tf);

    const size_t attn_smem = ATT_SMEM_WORDS * sizeof(uint32_t);
    static bool attr_done = false;
    if (!attr_done) {
        cudaFuncSetAttribute(tgemm_tf32_kernel<3 * D, D>,
                             cudaFuncAttributeMaxDynamicSharedMemorySize, GEMM_SMEM);
        cudaFuncSetAttribute(tgemm_tf32_kernel<D, D>,
                             cudaFuncAttributeMaxDynamicSharedMemorySize, GEMM_SMEM);
        cudaFuncSetAttribute(attn_mma_kernel,
                             cudaFuncAttributeMaxDynamicSharedMemorySize, (int)attn_smem);
        attr_done = true;
    }

    // 0) convert inputs to tf32 bit-patterns
    f32_to_tf32_kernel<<<(N_TOK * D / 4 + 255) / 256, 256>>>(hidden, hidtf, N_TOK * D / 4);
    f32_to_tf32_kernel<<<(D * 3 * D / 4 + 255) / 256, 256>>>(qkv_w, qkvwtf, D * 3 * D / 4);
    f32_to_tf32_kernel<<<(D * D / 4 + 255) / 256, 256>>>(proj_w, projwtf, D * D / 4);

    // 1) QKV GEMM + bias
    tgemm_tf32_kernel<3 * D, D><<<dim3((3 * D) / 128, N_TOK / 128), 256, GEMM_SMEM>>>(
        hidtf, qkvwtf, qkv_b, qkv);

    // 2) RoPE + split + tf32 precompute (q pre-scaled)
    {
        const int total = N_TOK * H * HK;
        rope_split_kernel<<<(total + 255) / 256, 256>>>(
            qkv, cosNK, sinNK, qhi, qlo, khi, klo, vtf);
    }

    // 3) mma flash attention -> tf32 output
    attn_mma_kernel<<<dim3(N_TOK / QTQ, H), 128, attn_smem>>>(
        qhi, qlo, khi, klo, vtf, cu, attntf);

    // 4) projection GEMM + bias -> d_out
    tgemm_tf32_kernel<D, D><<<dim3(D / 128, N_TOK / 128), 256, GEMM_SMEM>>>(
        attntf, projwtf, proj_b, out);
}

// round 6
// speedup vs baseline: 3.2572x; 1.2446x over previous
#include <cuda_runtime.h>
#include <cuda_bf16.h>
#include <cstdint>

// Problem constants
constexpr int N_TOK = 3072;
constexpr int D     = 1280;
constexpr int H     = 16;
constexpr int HK    = 80;     // head dim
constexpr int WPR   = HK / 2; // packed bf16 words per row (40)
constexpr int NSEG  = 8;
constexpr float SCALE = 0.111803398874989485f; // 80^-0.5

// ---------------- scratch ----------------
__device__ uint32_t g_hid_tf[N_TOK * D];        // tf32 of hidden
__device__ uint32_t g_qkvw_tf[D * 3 * D];       // tf32 of qkv_w
__device__ uint32_t g_projw_tf[D * D];          // tf32 of proj_w
__device__ float    g_qkv[N_TOK * 3 * D];       // [N][3][H][K] fp32
__device__ uint32_t g_qhib[H * N_TOK * WPR];    // bf16x2 hi of SCALE*rope(q)
__device__ uint32_t g_qlob[H * N_TOK * WPR];    // bf16x2 lo
__device__ uint32_t g_khib[H * N_TOK * WPR];
__device__ uint32_t g_klob[H * N_TOK * WPR];
__device__ uint32_t g_vtf[H * N_TOK * HK];      // tf32 v
__device__ uint32_t g_attn_tf[N_TOK * D];       // tf32 attention output [N][H*K]

// ---------------- helpers ----------------
__device__ __forceinline__ uint32_t f2tf32(float x) {
    uint32_t r;
    asm("cvt.rna.tf32.f32 %0, %1;" : "=r"(r) : "f"(x));
    return r;
}

__device__ __forceinline__ void mma_tf32(float c[4], const uint32_t a[4], const uint32_t b[2]) {
    asm volatile(
        "mma.sync.aligned.m16n8k8.row.col.f32.tf32.tf32.f32 "
        "{%0,%1,%2,%3}, {%4,%5,%6,%7}, {%8,%9}, {%0,%1,%2,%3};"
        : "+f"(c[0]), "+f"(c[1]), "+f"(c[2]), "+f"(c[3])
        : "r"(a[0]), "r"(a[1]), "r"(a[2]), "r"(a[3]), "r"(b[0]), "r"(b[1]));
}

__device__ __forceinline__ void mma_bf16(float c[4], const uint32_t a[4], const uint32_t b[2]) {
    asm volatile(
        "mma.sync.aligned.m16n8k16.row.col.f32.bf16.bf16.f32 "
        "{%0,%1,%2,%3}, {%4,%5,%6,%7}, {%8,%9}, {%0,%1,%2,%3};"
        : "+f"(c[0]), "+f"(c[1]), "+f"(c[2]), "+f"(c[3])
        : "r"(a[0]), "r"(a[1]), "r"(a[2]), "r"(a[3]), "r"(b[0]), "r"(b[1]));
}

__device__ __forceinline__ uint32_t bf16bits(float x) {
    const __nv_bfloat16 b = __float2bfloat16(x);
    return (uint32_t)*reinterpret_cast<const uint16_t*>(&b);
}
__device__ __forceinline__ float bf16val(uint32_t bits) {
    const uint16_t u = (uint16_t)bits;
    return __bfloat162float(*reinterpret_cast<const __nv_bfloat16*>(&u));
}

__device__ __forceinline__ uint32_t smem_addr(const void* p) {
    return (uint32_t)__cvta_generic_to_shared(p);
}
#define CP_ASYNC16(dst, src) \
    asm volatile("cp.async.cg.shared.global [%0], [%1], 16;" :: "r"(dst), "l"(src))
#define CP_COMMIT() asm volatile("cp.async.commit_group;")
#define CP_WAIT1()  asm volatile("cp.async.wait_group 1;")

// ---------------- f32 -> tf32 bulk convert ----------------
__global__ void __launch_bounds__(256) f32_to_tf32_kernel(
    const float* __restrict__ s, uint32_t* __restrict__ d, int n4)
{
    const int i = blockIdx.x * blockDim.x + threadIdx.x;
    if (i >= n4) return;
    const float4 x = reinterpret_cast<const float4*>(s)[i];
    uint4 y;
    y.x = f2tf32(x.x); y.y = f2tf32(x.y); y.z = f2tf32(x.z); y.w = f2tf32(x.w);
    reinterpret_cast<uint4*>(d)[i] = y;
}

// ---------------- tf32 GEMM, cp.async 3-stage (unchanged) ----------------
constexpr int ASTR = 36;
constexpr int BSTR = 136;
constexpr int A_WORDS = 128 * ASTR;
constexpr int B_WORDS = 32 * BSTR;
constexpr int STAGE_WORDS = A_WORDS + B_WORDS;
constexpr int GEMM_SMEM = 3 * STAGE_WORDS * 4;

template<int NN, int KD>
__global__ void __launch_bounds__(256) tgemm_tf32_kernel(
    const uint32_t* __restrict__ A, const uint32_t* __restrict__ B,
    const float* __restrict__ bias, float* __restrict__ C)
{
    extern __shared__ uint32_t smem[];

    const int tid  = threadIdx.x;
    const int lane = tid & 31;
    const int w    = tid >> 5;
    const int g    = lane >> 2;
    const int qd   = lane & 3;
    const int wm   = w >> 2;
    const int wn   = w & 3;
    const int bm   = blockIdx.y * 128;
    const int bn   = blockIdx.x * 128;

    const int ar = tid >> 1;
    const int ah = (tid & 1) * 16;
    const int br = tid >> 3;
    const int bc = tid & 7;

    auto issue = [&](int kt) {
        const int k0 = kt * 32;
        uint32_t* as = smem + (kt % 3) * STAGE_WORDS;
        uint32_t* bs = as + A_WORDS;
        #pragma unroll
        for (int i = 0; i < 4; i++) {
            const uint32_t dst = smem_addr(&as[ar * ASTR + ah + i * 4]);
            CP_ASYNC16(dst, &A[(size_t)(bm + ar) * KD + k0 + ah + i * 4]);
        }
        #pragma unroll
        for (int i = 0; i < 4; i++) {
            const int col = (bc + 8 * i) * 4;
            const uint32_t dst = smem_addr(&bs[br * BSTR + col]);
            CP_ASYNC16(dst, &B[(size_t)(k0 + br) * NN + bn + col]);
        }
        CP_COMMIT();
    };

    float acc[4][4][4] = {};

    issue(0);
    issue(1);

    constexpr int KT = KD / 32;
    for (int kt = 0; kt < KT; kt++) {
        CP_WAIT1();
        __syncthreads();
        if (kt + 2 < KT) issue(kt + 2);

        const uint32_t* as = smem + (kt % 3) * STAGE_WORDS;
        const uint32_t* bs = as + A_WORDS;

        #pragma unroll
        for (int kk = 0; kk < 32; kk += 8) {
            uint32_t af[4][4], bf[4][2];
            #pragma unroll
            for (int mi = 0; mi < 4; mi++) {
                const int r0 = (wm * 64 + mi * 16 + g) * ASTR;
                af[mi][0] = as[r0 + kk + qd];
                af[mi][1] = as[r0 + 8 * ASTR + kk + qd];
                af[mi][2] = as[r0 + kk + 4 + qd];
                af[mi][3] = as[r0 + 8 * ASTR + kk + 4 + qd];
            }
            #pragma unroll
            for (int ni = 0; ni < 4; ni++) {
                const int c0 = wn * 32 + ni * 8 + g;
                bf[ni][0] = bs[(kk + qd) * BSTR + c0];
                bf[ni][1] = bs[(kk + 4 + qd) * BSTR + c0];
            }
            #pragma unroll
            for (int mi = 0; mi < 4; mi++)
                #pragma unroll
                for (int ni = 0; ni < 4; ni++)
                    mma_tf32(acc[mi][ni], af[mi], bf[ni]);
        }
        __syncthreads();
    }

    #pragma unroll
    for (int mi = 0; mi < 4; mi++) {
        const int row = bm + wm * 64 + mi * 16 + g;
        #pragma unroll
        for (int ni = 0; ni < 4; ni++) {
            const int col = bn + wn * 32 + ni * 8 + 2 * qd;
            const float2 bb = *reinterpret_cast<const float2*>(&bias[col]);
            float2 o0, o1;
            o0.x = acc[mi][ni][0] + bb.x; o0.y = acc[mi][ni][1] + bb.y;
            o1.x = acc[mi][ni][2] + bb.x; o1.y = acc[mi][ni][3] + bb.y;
            *reinterpret_cast<float2*>(&C[(size_t)row * NN + col]) = o0;
            *reinterpret_cast<float2*>(&C[(size_t)(row + 8) * NN + col]) = o1;
        }
    }
}

// ---------------- RoPE + split + bf16 hi/lo (q/k) + tf32 (v) precompute ----------------
// one thread per packed word (2 consecutive k-elements)
__global__ void __launch_bounds__(256) rope_split_kernel(
    const float* __restrict__ qkv, const float* __restrict__ cosNK,
    const float* __restrict__ sinNK,
    uint32_t* __restrict__ qhib, uint32_t* __restrict__ qlob,
    uint32_t* __restrict__ khib, uint32_t* __restrict__ klob,
    uint32_t* __restrict__ vtf)
{
    const int idx = blockIdx.x * blockDim.x + threadIdx.x;
    if (idx >= N_TOK * H * WPR) return;
    const int wd = idx % WPR;
    const int h  = (idx / WPR) % H;
    const int n  = idx / (WPR * H);

    const float* base = qkv + (size_t)n * 3 * H * HK;

    float qr[2], kr[2], vv[2];
    #pragma unroll
    for (int e = 0; e < 2; e++) {
        const int kk = 2 * wd + e;
        const float c = cosNK[n * HK + kk];
        const float s = sinNK[n * HK + kk];
        const int off  = h * HK + kk;
        const int krot = (kk < HK / 2) ? kk + HK / 2 : kk - HK / 2;
        const float sg = (kk < HK / 2) ? -1.f : 1.f;
        const int offr = h * HK + krot;

        const float qv  = base[off];
        const float kv  = base[H * HK + off];
        vv[e]           = base[2 * H * HK + off];
        const float qvr = base[offr];
        const float kvr = base[H * HK + offr];

        qr[e] = (qv * c + sg * qvr * s) * SCALE;
        kr[e] = kv * c + sg * kvr * s;
    }

    uint32_t qh[2], ql[2], kh[2], kl[2];
    #pragma unroll
    for (int e = 0; e < 2; e++) {
        qh[e] = bf16bits(qr[e]);
        ql[e] = bf16bits(qr[e] - bf16val(qh[e]));
        kh[e] = bf16bits(kr[e]);
        kl[e] = bf16bits(kr[e] - bf16val(kh[e]));
    }

    const size_t ow = (size_t)h * N_TOK * WPR + (size_t)n * WPR + wd;
    qhib[ow] = (qh[1] << 16) | qh[0];
    qlob[ow] = (ql[1] << 16) | ql[0];
    khib[ow] = (kh[1] << 16) | kh[0];
    klob[ow] = (kl[1] << 16) | kl[0];

    const size_t ov = (size_t)h * N_TOK * HK + (size_t)n * HK + 2 * wd;
    vtf[ov]     = f2tf32(vv[0]);
    vtf[ov + 1] = f2tf32(vv[1]);
}

// ---------------- mma flash attention: bf16 hi/lo QK, tf32 PV ----------------
constexpr int QTQ  = 64;
constexpr int KTK  = 32;
constexpr int QSTR = 44;  // packed q/k stride: (12g+qd) mod 32 conflict-free
constexpr int VSTR = 88;  // v stride: (24qd+g) conflict-free
constexpr int PST  = 36;  // P stride: (4g+qd) conflict-free

constexpr int ATT_SMEM_WORDS =
    2 * QTQ * QSTR      // qhi, qlo   5632
    + 2 * KTK * QSTR    // khi, klo   2816
    + KTK * VSTR        // v          2816
    + 4 * 16 * PST      // P          2304
    + 2 * QTQ + 2;      // rs, re, blk

__global__ void __launch_bounds__(128, 4) attn_mma_kernel(
    const uint32_t* __restrict__ gqhi, const uint32_t* __restrict__ gqlo,
    const uint32_t* __restrict__ gkhi, const uint32_t* __restrict__ gklo,
    const uint32_t* __restrict__ gvtf, const int* __restrict__ cu,
    uint32_t* __restrict__ attn_tf)
{
    extern __shared__ uint32_t sm[];
    uint32_t* qhiS = sm;
    uint32_t* qloS = qhiS + QTQ * QSTR;
    uint32_t* khiS = qloS + QTQ * QSTR;
    uint32_t* kloS = khiS + KTK * QSTR;
    uint32_t* vS   = kloS + KTK * QSTR;
    uint32_t* pS   = vS + KTK * VSTR;
    int*      rs   = (int*)(pS + 4 * 16 * PST);
    int*      re   = rs + QTQ;
    int*      blk  = re + QTQ;

    const int h    = blockIdx.y;
    const int q0   = blockIdx.x * QTQ;
    const int tid  = threadIdx.x;
    const int w    = tid >> 5;
    const int lane = tid & 31;
    const int g    = lane >> 2;
    const int qd   = lane & 3;

    if (tid < QTQ) {
        const int n = q0 + tid;
        int lo = 0, hi = N_TOK;
        #pragma unroll
        for (int sgi = 0; sgi < NSEG; sgi++) {
            const int a = cu[sgi], b = cu[sgi + 1];
            if (n >= a && n < b) { lo = a; hi = b; }
        }
        rs[tid] = lo; re[tid] = hi;
    }
    __syncthreads();
    if (tid == 0) {
        int lo = rs[0], hi = re[0];
        #pragma unroll
        for (int r = 1; r < QTQ; r++) { lo = min(lo, rs[r]); hi = max(hi, re[r]); }
        blk[0] = lo; blk[1] = hi;
    }

    // per-warp bounds (16 rows)
    int wlo = N_TOK, whi = 0;
    #pragma unroll
    for (int r = 0; r < 16; r++) {
        wlo = min(wlo, rs[w * 16 + r]);
        whi = max(whi, re[w * 16 + r]);
    }

    // stage Q (packed bf16x2, uint4 copies)
    const size_t hb40 = (size_t)h * N_TOK * WPR;
    const size_t hb80 = (size_t)h * N_TOK * HK;
    for (int i = tid; i < QTQ * (WPR / 4); i += 128) {
        const int r  = i / (WPR / 4);
        const int c4 = (i % (WPR / 4)) * 4;
        const size_t go = hb40 + (size_t)(q0 + r) * WPR + c4;
        *reinterpret_cast<uint4*>(&qhiS[r * QSTR + c4]) = *reinterpret_cast<const uint4*>(&gqhi[go]);
        *reinterpret_cast<uint4*>(&qloS[r * QSTR + c4]) = *reinterpret_cast<const uint4*>(&gqlo[go]);
    }
    __syncthreads();

    const int rowA = w * 16 + g, rowB = rowA + 8;
    const int rsA = rs[rowA], reA = re[rowA];
    const int rsB = rs[rowB], reB = re[rowB];
    const int lo = blk[0], hi = blk[1];

    float miA = -1e30f, liA = 0.f, miB = -1e30f, liB = 0.f;
    float acc[10][4] = {};
    uint32_t* pw = pS + w * (16 * PST);

    for (int kc = lo; kc < hi; kc += KTK) {
        __syncthreads();
        for (int i = tid; i < KTK * (WPR / 4); i += 128) {
            const int r  = i / (WPR / 4);
            const int c4 = (i % (WPR / 4)) * 4;
            const int m  = kc + r;
            uint4 kh4 = {0, 0, 0, 0}, kl4 = {0, 0, 0, 0};
            if (m < hi) {
                const size_t go = hb40 + (size_t)m * WPR + c4;
                kh4 = *reinterpret_cast<const uint4*>(&gkhi[go]);
                kl4 = *reinterpret_cast<const uint4*>(&gklo[go]);
            }
            *reinterpret_cast<uint4*>(&khiS[r * QSTR + c4]) = kh4;
            *reinterpret_cast<uint4*>(&kloS[r * QSTR + c4]) = kl4;
        }
        for (int i = tid; i < KTK * (HK / 4); i += 128) {
            const int r  = i / (HK / 4);
            const int c4 = (i % (HK / 4)) * 4;
            const int m  = kc + r;
            uint4 vv4 = {0, 0, 0, 0};
            if (m < hi) {
                const size_t go = hb80 + (size_t)m * HK + c4;
                vv4 = *reinterpret_cast<const uint4*>(&gvtf[go]);
            }
            *reinterpret_cast<uint4*>(&vS[r * VSTR + c4]) = vv4;
        }
        __syncthreads();

        if (kc + KTK <= wlo || kc >= whi) continue;   // warp has no overlap

        // ---- S = Q K^T (3x bf16 hi/lo, k16 slabs) ----
        float s[4][4] = {};
        #pragma unroll
        for (int sl = 0; sl < 5; sl++) {
            const int base = sl * 8;
            uint32_t ah[4], al[4];
            const int rA = rowA * QSTR + base, rB = rowB * QSTR + base;
            ah[0] = qhiS[rA + qd];
            ah[1] = qhiS[rB + qd];
            ah[2] = qhiS[rA + 4 + qd];
            ah[3] = qhiS[rB + 4 + qd];
            al[0] = qloS[rA + qd];
            al[1] = qloS[rB + qd];
            al[2] = qloS[rA + 4 + qd];
            al[3] = qloS[rB + 4 + qd];
            #pragma unroll
            for (int nt = 0; nt < 4; nt++) {
                const int kr = (nt * 8 + g) * QSTR + base;
                uint32_t bh[2], bl[2];
                bh[0] = khiS[kr + qd];
                bh[1] = khiS[kr + 4 + qd];
                bl[0] = kloS[kr + qd];
                bl[1] = kloS[kr + 4 + qd];
                mma_bf16(s[nt], ah, bh);
                mma_bf16(s[nt], ah, bl);
                mma_bf16(s[nt], al, bh);
            }
        }

        // ---- register softmax ----
        float mxA = -1e30f, mxB = -1e30f;
        #pragma unroll
        for (int nt = 0; nt < 4; nt++) {
            const int c0 = kc + nt * 8 + 2 * qd;
            const int c1 = c0 + 1;
            mxA = fmaxf(mxA, fmaxf((c0 >= rsA && c0 < reA) ? s[nt][0] : -1e30f,
                                   (c1 >= rsA && c1 < reA) ? s[nt][1] : -1e30f));
            mxB = fmaxf(mxB, fmaxf((c0 >= rsB && c0 < reB) ? s[nt][2] : -1e30f,
                                   (c1 >= rsB && c1 < reB) ? s[nt][3] : -1e30f));
        }
        #pragma unroll
        for (int off = 1; off <= 2; off <<= 1) {
            mxA = fmaxf(mxA, __shfl_xor_sync(0xffffffffu, mxA, off));
            mxB = fmaxf(mxB, __shfl_xor_sync(0xffffffffu, mxB, off));
        }
        const float nmA = fmaxf(miA, mxA), nmB = fmaxf(miB, mxB);
        const float crA = __expf(miA - nmA), crB = __expf(miB - nmB);
        float sumA = 0.f, sumB = 0.f;
        #pragma unroll
        for (int nt = 0; nt < 4; nt++) {
            const int c0 = kc + nt * 8 + 2 * qd;
            const int c1 = c0 + 1;
            s[nt][0] = (c0 >= rsA && c0 < reA) ? __expf(s[nt][0] - nmA) : 0.f;
            s[nt][1] = (c1 >= rsA && c1 < reA) ? __expf(s[nt][1] - nmA) : 0.f;
            s[nt][2] = (c0 >= rsB && c0 < reB) ? __expf(s[nt][2] - nmB) : 0.f;
            s[nt][3] = (c1 >= rsB && c1 < reB) ? __expf(s[nt][3] - nmB) : 0.f;
            sumA += s[nt][0] + s[nt][1];
            sumB += s[nt][2] + s[nt][3];
        }
        #pragma unroll
        for (int off = 1; off <= 2; off <<= 1) {
            sumA += __shfl_xor_sync(0xffffffffu, sumA, off);
            sumB += __shfl_xor_sync(0xffffffffu, sumB, off);
        }
        liA = liA * crA + sumA; miA = nmA;
        liB = liB * crB + sumB; miB = nmB;

        #pragma unroll
        for (int nt = 0; nt < 10; nt++) {
            acc[nt][0] *= crA; acc[nt][1] *= crA;
            acc[nt][2] *= crB; acc[nt][3] *= crB;
        }

        // ---- P -> warp-private smem (tf32), then PV (tf32) ----
        #pragma unroll
        for (int nt = 0; nt < 4; nt++) {
            const int cb = nt * 8 + 2 * qd;
            uint2 pa, pb;
            pa.x = f2tf32(s[nt][0]); pa.y = f2tf32(s[nt][1]);
            pb.x = f2tf32(s[nt][2]); pb.y = f2tf32(s[nt][3]);
            *reinterpret_cast<uint2*>(&pw[g * PST + cb])       = pa;
            *reinterpret_cast<uint2*>(&pw[(g + 8) * PST + cb]) = pb;
        }
        __syncwarp();

        #pragma unroll
        for (int k8 = 0; k8 < KTK; k8 += 8) {
            uint32_t a[4];
            a[0] = pw[g * PST + k8 + qd];
            a[1] = pw[(g + 8) * PST + k8 + qd];
            a[2] = pw[g * PST + k8 + 4 + qd];
            a[3] = pw[(g + 8) * PST + k8 + 4 + qd];
            #pragma unroll
            for (int nt = 0; nt < 10; nt++) {
                uint32_t b[2];
                b[0] = vS[(k8 + qd) * VSTR + nt * 8 + g];
                b[1] = vS[(k8 + 4 + qd) * VSTR + nt * 8 + g];
                mma_tf32(acc[nt], a, b);
            }
        }
        __syncwarp();
    }

    // ---- epilogue: normalize, write tf32 [N][H*K] ----
    const float invA = 1.f / liA, invB = 1.f / liB;
    uint32_t* dA = attn_tf + (size_t)(q0 + rowA) * (H * HK) + h * HK;
    uint32_t* dB = attn_tf + (size_t)(q0 + rowB) * (H * HK) + h * HK;
    #pragma unroll
    for (int nt = 0; nt < 10; nt++) {
        const int col = nt * 8 + 2 * qd;
        dA[col]     = f2tf32(acc[nt][0] * invA);
        dA[col + 1] = f2tf32(acc[nt][1] * invA);
        dB[col]     = f2tf32(acc[nt][2] * invB);
        dB[col + 1] = f2tf32(acc[nt][3] * invB);
    }
}

// ---------------- launch ----------------
extern "C" void kernel_launch(void* const* d_in, const int* in_sizes, int n_in,
                              void* d_out, int out_size)
{
    const float* hidden = (const float*)d_in[0];
    const int*   cu     = (const int*)  d_in[1];
    const float* cosNK  = (const float*)d_in[2];
    const float* sinNK  = (const float*)d_in[3];
    const float* qkv_w  = (const float*)d_in[4];
    const float* qkv_b  = (const float*)d_in[5];
    const float* proj_w = (const float*)d_in[6];
    const float* proj_b = (const float*)d_in[7];
    float* out = (float*)d_out;

    float *qkv;
    uint32_t *hidtf, *qkvwtf, *projwtf, *qhib, *qlob, *khib, *klob, *vtf, *attntf;
    cudaGetSymbolAddress((void**)&hidtf,  g_hid_tf);
    cudaGetSymbolAddress((void**)&qkvwtf, g_qkvw_tf);
    cudaGetSymbolAddress((void**)&projwtf,g_projw_tf);
    cudaGetSymbolAddress((void**)&qkv,    g_qkv);
    cudaGetSymbolAddress((void**)&qhib,   g_qhib);
    cudaGetSymbolAddress((void**)&qlob,   g_qlob);
    cudaGetSymbolAddress((void**)&khib,   g_khib);
    cudaGetSymbolAddress((void**)&klob,   g_klob);
    cudaGetSymbolAddress((void**)&vtf,    g_vtf);
    cudaGetSymbolAddress((void**)&attntf, g_attn_tf);

    const size_t attn_smem = ATT_SMEM_WORDS * sizeof(uint32_t);
    static bool attr_done = false;
    if (!attr_done) {
        cudaFuncSetAttribute(tgemm_tf32_kernel<3 * D, D>,
                             cudaFuncAttributeMaxDynamicSharedMemorySize, GEMM_SMEM);
        cudaFuncSetAttribute(tgemm_tf32_kernel<D, D>,
                             cudaFuncAttributeMaxDynamicSharedMemorySize, GEMM_SMEM);
        cudaFuncSetAttribute(attn_mma_kernel,
                             cudaFuncAttributeMaxDynamicSharedMemorySize, (int)attn_smem);
        attr_done = true;
    }

    // 0) convert inputs to tf32 bit-patterns
    f32_to_tf32_kernel<<<(N_TOK * D / 4 + 255) / 256, 256>>>(hidden, hidtf, N_TOK * D / 4);
    f32_to_tf32_kernel<<<(D * 3 * D / 4 + 255) / 256, 256>>>(qkv_w, qkvwtf, D * 3 * D / 4);
    f32_to_tf32_kernel<<<(D * D / 4 + 255) / 256, 256>>>(proj_w, projwtf, D * D / 4);

    // 1) QKV GEMM + bias
    tgemm_tf32_kernel<3 * D, D><<<dim3((3 * D) / 128, N_TOK / 128), 256, GEMM_SMEM>>>(
        hidtf, qkvwtf, qkv_b, qkv);

    // 2) RoPE + split + bf16 hi/lo + tf32 v
    {
        const int total = N_TOK * H * WPR;
        rope_split_kernel<<<(total + 255) / 256, 256>>>(
            qkv, cosNK, sinNK, qhib, qlob, khib, klob, vtf);
    }

    // 3) mma flash attention -> tf32 output
    attn_mma_kernel<<<dim3(N_TOK / QTQ, H), 128, attn_smem>>>(
        qhib, qlob, khib, klob, vtf, cu, attntf);

    // 4) projection GEMM + bias -> d_out
    tgemm_tf32_kernel<D, D><<<dim3(D / 128, N_TOK / 128), 256, GEMM_SMEM>>>(
        attntf, projwtf, proj_b, out);
}